// round 12
// baseline (speedup 1.0000x reference)
#include <cuda_runtime.h>
#include <cuda_fp16.h>
#include <cstdint>

#define NN 10000
#define NE 160000
#define F 512

// ==================== scratch (device globals) ====================
__device__ int   g_ivec[3][NN];
#define g_deg_out (g_ivec[0])
#define g_deg_in  (g_ivec[1])
#define g_cnt     (g_ivec[2])
__device__ int   g_off[NN + 1];
__device__ int   g_bsum[40];
__device__ int   g_csr_src[NE];
__device__ float g_csr_w[NE];
__device__ __half g_x16[(size_t)NN * F];    // fp16 x, later fp16 h2
__device__ __half g_hf16[(size_t)NN * F];   // fp16 h1
__device__ __half g_A16[(size_t)NN * F];    // Y1, then aggregated GEMM A operand
__device__ __half g_W1h[F * F], g_W2h[F * F], g_W3h[F * F];

// ==================== PTX helpers ====================
__device__ __forceinline__ uint32_t smem_to_u32(const void* p) {
    uint32_t a;
    asm("{ .reg .u64 t; cvta.to.shared.u64 t, %1; cvt.u32.u64 %0, t; }" : "=r"(a) : "l"(p));
    return a;
}
__device__ __forceinline__ void cp_async16(uint32_t dst, const void* src, int sz) {
    asm volatile("cp.async.cg.shared.global [%0], [%1], 16, %2;"
        :: "r"(dst), "l"(src), "r"(sz) : "memory");
}
__device__ __forceinline__ void ldsm4(uint32_t* r, uint32_t addr) {
    asm volatile("ldmatrix.sync.aligned.m8n8.x4.shared.b16 {%0,%1,%2,%3}, [%4];"
        : "=r"(r[0]), "=r"(r[1]), "=r"(r[2]), "=r"(r[3]) : "r"(addr));
}
__device__ __forceinline__ void mma_f16(float* d, const uint32_t* a, const uint32_t* b) {
    asm volatile(
        "mma.sync.aligned.m16n8k16.row.col.f32.f16.f16.f32 "
        "{%0,%1,%2,%3}, {%4,%5,%6,%7}, {%8,%9}, {%0,%1,%2,%3};"
        : "+f"(d[0]), "+f"(d[1]), "+f"(d[2]), "+f"(d[3])
        : "r"(a[0]), "r"(a[1]), "r"(a[2]), "r"(a[3]), "r"(b[0]), "r"(b[1]));
}

// ==================== setup kernels ====================
// 4 edges per thread, vectorized loads
__global__ void degree_kernel(const int* __restrict__ src, const int* __restrict__ dst) {
    int i = blockIdx.x * blockDim.x + threadIdx.x;   // int4 index
    if (i < NE / 4) {
        int4 s = reinterpret_cast<const int4*>(src)[i];
        int4 d = reinterpret_cast<const int4*>(dst)[i];
        atomicAdd(&g_deg_out[s.x], 1); atomicAdd(&g_deg_out[s.y], 1);
        atomicAdd(&g_deg_out[s.z], 1); atomicAdd(&g_deg_out[s.w], 1);
        atomicAdd(&g_deg_in[d.x], 1);  atomicAdd(&g_deg_in[d.y], 1);
        atomicAdd(&g_deg_in[d.z], 1);  atomicAdd(&g_deg_in[d.w], 1);
    }
}

__global__ void scan1_kernel() {
    __shared__ int wsum[8];
    int tid = threadIdx.x;
    int idx = blockIdx.x * 256 + tid;
    int v = (idx < NN) ? g_deg_in[idx] : 0;
    int x = v;
    #pragma unroll
    for (int d = 1; d < 32; d <<= 1) {
        int y = __shfl_up_sync(0xffffffffu, x, d);
        if ((tid & 31) >= d) x += y;
    }
    if ((tid & 31) == 31) wsum[tid >> 5] = x;
    __syncthreads();
    if (tid < 8) {
        int w = wsum[tid];
        #pragma unroll
        for (int d = 1; d < 8; d <<= 1) {
            int y = __shfl_up_sync(0xffu, w, d);
            if (tid >= d) w += y;
        }
        wsum[tid] = w;
    }
    __syncthreads();
    int incl = x + ((tid >= 32) ? wsum[(tid >> 5) - 1] : 0);
    if (idx <= NN) g_off[idx] = incl - v;
    if (tid == 255) g_bsum[blockIdx.x] = incl;
}

__global__ void scan2_kernel() {
    __shared__ int pref[41];
    int tid = threadIdx.x;
    if (tid == 0) {
        int s = 0;
        #pragma unroll
        for (int b = 0; b < 40; ++b) { pref[b] = s; s += g_bsum[b]; }
        pref[40] = s;
    }
    __syncthreads();
    int idx = blockIdx.x * 256 + tid;
    if (idx < NN) g_off[idx] += pref[blockIdx.x];
    if (idx == NN - 1) g_off[NN] = pref[40];
}

// 2 edges per thread
__global__ void scatter_kernel(const int* __restrict__ src, const int* __restrict__ dst) {
    int i = blockIdx.x * blockDim.x + threadIdx.x;
    if (i < NE / 2) {
        int2 s2 = reinterpret_cast<const int2*>(src)[i];
        int2 d2 = reinterpret_cast<const int2*>(dst)[i];
        int p0 = g_off[d2.x] + atomicAdd(&g_cnt[d2.x], 1);
        g_csr_src[p0] = s2.x;
        g_csr_w[p0]   = rsqrtf((float)g_deg_out[s2.x]);
        int p1 = g_off[d2.y] + atomicAdd(&g_cnt[d2.y], 1);
        g_csr_src[p1] = s2.y;
        g_csr_w[p1]   = rsqrtf((float)g_deg_out[s2.y]);
    }
}

// x fp32 -> fp16
__global__ void xconvert_kernel(const float* __restrict__ x, __half* __restrict__ o) {
    int i = blockIdx.x * blockDim.x + threadIdx.x;
    float4 v = reinterpret_cast<const float4*>(x)[i];
    __half2 a = __floats2half2_rn(v.x, v.y);
    __half2 b = __floats2half2_rn(v.z, v.w);
    uint32_t ua = *reinterpret_cast<uint32_t*>(&a);
    uint32_t ub = *reinterpret_cast<uint32_t*>(&b);
    reinterpret_cast<uint2*>(o)[i] = make_uint2(ua, ub);
}

// W k-major -> transposed fp16 Wt[n][k]; grid.z picks 1 (W1 only) or 2 (W2,W3)
__global__ void wsplit_kernel(const float* __restrict__ Wa, __half* __restrict__ Oa,
                              const float* __restrict__ Wb, __half* __restrict__ Ob) {
    const float* W = (blockIdx.z == 0) ? Wa : Wb;
    __half* Oh = (blockIdx.z == 0) ? Oa : Ob;
    __shared__ float t[32][33];
    int n = blockIdx.x * 32 + threadIdx.x;
    int k = blockIdx.y * 32 + threadIdx.y;
    t[threadIdx.y][threadIdx.x] = W[(size_t)k * F + n];
    __syncthreads();
    int on = blockIdx.x * 32 + threadIdx.y;
    int ok = blockIdx.y * 32 + threadIdx.x;
    Oh[(size_t)on * F + ok] = __float2half_rn(t[threadIdx.x][threadIdx.y]);
}

// ==================== aggregation: 2 nodes per CTA (256 thr) ====================
__global__ __launch_bounds__(256) void agg_kernel(const __half* __restrict__ x,
                                                  __half* __restrict__ o,
                                                  const float* __restrict__ bias,
                                                  int relu) {
    int node = blockIdx.x * 2 + (threadIdx.x >> 7);
    int tid  = threadIdx.x & 127;
    if (node >= NN) return;
    int beg = g_off[node];
    int end = g_off[node + 1];
    const uint2* x2 = reinterpret_cast<const uint2*>(x);
    float4 acc = make_float4(0.f, 0.f, 0.f, 0.f);
    int i = beg;
    for (; i + 4 <= end; i += 4) {
        int   s0 = __ldg(&g_csr_src[i + 0]);
        int   s1 = __ldg(&g_csr_src[i + 1]);
        int   s2 = __ldg(&g_csr_src[i + 2]);
        int   s3 = __ldg(&g_csr_src[i + 3]);
        float w0 = __ldg(&g_csr_w[i + 0]);
        float w1 = __ldg(&g_csr_w[i + 1]);
        float w2 = __ldg(&g_csr_w[i + 2]);
        float w3 = __ldg(&g_csr_w[i + 3]);
        uint2 u0 = x2[(size_t)s0 * 128 + tid];
        uint2 u1 = x2[(size_t)s1 * 128 + tid];
        uint2 u2 = x2[(size_t)s2 * 128 + tid];
        uint2 u3 = x2[(size_t)s3 * 128 + tid];
        float2 a0 = __half22float2(*reinterpret_cast<__half2*>(&u0.x));
        float2 b0 = __half22float2(*reinterpret_cast<__half2*>(&u0.y));
        float2 a1 = __half22float2(*reinterpret_cast<__half2*>(&u1.x));
        float2 b1 = __half22float2(*reinterpret_cast<__half2*>(&u1.y));
        float2 a2 = __half22float2(*reinterpret_cast<__half2*>(&u2.x));
        float2 b2 = __half22float2(*reinterpret_cast<__half2*>(&u2.y));
        float2 a3 = __half22float2(*reinterpret_cast<__half2*>(&u3.x));
        float2 b3 = __half22float2(*reinterpret_cast<__half2*>(&u3.y));
        acc.x = fmaf(w0, a0.x, acc.x); acc.y = fmaf(w0, a0.y, acc.y);
        acc.z = fmaf(w0, b0.x, acc.z); acc.w = fmaf(w0, b0.y, acc.w);
        acc.x = fmaf(w1, a1.x, acc.x); acc.y = fmaf(w1, a1.y, acc.y);
        acc.z = fmaf(w1, b1.x, acc.z); acc.w = fmaf(w1, b1.y, acc.w);
        acc.x = fmaf(w2, a2.x, acc.x); acc.y = fmaf(w2, a2.y, acc.y);
        acc.z = fmaf(w2, b2.x, acc.z); acc.w = fmaf(w2, b2.y, acc.w);
        acc.x = fmaf(w3, a3.x, acc.x); acc.y = fmaf(w3, a3.y, acc.y);
        acc.z = fmaf(w3, b3.x, acc.z); acc.w = fmaf(w3, b3.y, acc.w);
    }
    for (; i < end; ++i) {
        int   s = __ldg(&g_csr_src[i]);
        float w = __ldg(&g_csr_w[i]);
        uint2 u = x2[(size_t)s * 128 + tid];
        float2 a = __half22float2(*reinterpret_cast<__half2*>(&u.x));
        float2 b = __half22float2(*reinterpret_cast<__half2*>(&u.y));
        acc.x = fmaf(w, a.x, acc.x); acc.y = fmaf(w, a.y, acc.y);
        acc.z = fmaf(w, b.x, acc.z); acc.w = fmaf(w, b.y, acc.w);
    }
    float ni = (end > beg) ? rsqrtf((float)(end - beg)) : 0.f;
    float r0 = acc.x * ni, r1 = acc.y * ni, r2 = acc.z * ni, r3 = acc.w * ni;
    if (bias) {
        float4 bv = reinterpret_cast<const float4*>(bias)[tid];
        r0 += bv.x; r1 += bv.y; r2 += bv.z; r3 += bv.w;
    }
    if (relu) {
        r0 = fmaxf(r0, 0.f); r1 = fmaxf(r1, 0.f);
        r2 = fmaxf(r2, 0.f); r3 = fmaxf(r3, 0.f);
    }
    __half2 p0 = __floats2half2_rn(r0, r1);
    __half2 p1 = __floats2half2_rn(r2, r3);
    uint2 u = make_uint2(*reinterpret_cast<uint32_t*>(&p0), *reinterpret_cast<uint32_t*>(&p1));
    reinterpret_cast<uint2*>(o + (size_t)node * F)[tid] = u;
}

// ==================== mma.sync GEMM: C = A@B^T (+bias, +relu) ====================
#define STAGE_BYTES 32768
#define NSTAGE 3
#define GEMM_SMEM (NSTAGE * STAGE_BYTES)

__device__ __forceinline__ void load_stage(
    uint32_t s, int m0, int n0, int M, int k0, int tid,
    const __half* __restrict__ A, const __half* __restrict__ B)
{
    #pragma unroll
    for (int i = 0; i < 4; ++i) {
        int v = tid + i * 256;
        int row = v >> 3, c = v & 7;
        uint32_t phys = (uint32_t)(row * 128 + ((c ^ (row & 7)) << 4));
        size_t gA = (size_t)(m0 + row) * F + k0 + c * 8;
        int sz = (m0 + row < M) ? 16 : 0;
        cp_async16(s + phys, A + gA, sz);
        size_t gB = (size_t)(n0 + row) * F + k0 + c * 8;
        cp_async16(s + 16384 + phys, B + gB, 16);
    }
    asm volatile("cp.async.commit_group;" ::: "memory");
}

__global__ __launch_bounds__(256, 2) void gemm_mma(
    const __half* __restrict__ A,
    const __half* __restrict__ B, const float* __restrict__ bias,
    float* __restrict__ C, __half* __restrict__ C16,
    const __half* __restrict__ B2, const float* __restrict__ bias2, float* __restrict__ C2,
    int M, int relu, int dual)
{
    extern __shared__ char smem[];
    const uint32_t sb = smem_to_u32(smem);
    const int tid = threadIdx.x;
    const int wid = tid >> 5, lid = tid & 31;
    int nb = blockIdx.x;
    if (dual && nb >= 4) {
        nb -= 4;
        B = B2; bias = bias2; C = C2; C16 = nullptr; relu = 0;
    }
    const int m0 = blockIdx.y * 128, n0 = nb * 128;
    const int wm = (wid & 3) * 32;
    const int wn = (wid >> 2) * 64;

    float acc[2][8][4];
    #pragma unroll
    for (int a = 0; a < 2; ++a)
        #pragma unroll
        for (int b = 0; b < 8; ++b)
            #pragma unroll
            for (int c = 0; c < 4; ++c) acc[a][b][c] = 0.f;

    load_stage(sb, m0, n0, M, 0, tid, A, B);
    load_stage(sb + STAGE_BYTES, m0, n0, M, 64, tid, A, B);

    const int NCH = F / 64;   // 8
    for (int ch = 0; ch < NCH; ++ch) {
        asm volatile("cp.async.wait_group 1;" ::: "memory");
        __syncthreads();
        if (ch + 2 < NCH)
            load_stage(sb + ((ch + 2) % NSTAGE) * STAGE_BYTES, m0, n0, M, (ch + 2) * 64, tid, A, B);
        else
            asm volatile("cp.async.commit_group;" ::: "memory");

        const uint32_t s = sb + (ch % NSTAGE) * STAGE_BYTES;
        #pragma unroll
        for (int kk = 0; kk < 4; ++kk) {
            uint32_t af[2][4];
            #pragma unroll
            for (int mt = 0; mt < 2; ++mt) {
                int row = wm + mt * 16 + (lid & 15);
                int c = kk * 2 + ((lid >> 4) & 1);
                ldsm4(af[mt], s + row * 128 + ((c ^ (row & 7)) << 4));
            }
            #pragma unroll
            for (int p = 0; p < 4; ++p) {
                int row = wn + p * 16 + (lid & 7) + (((lid >> 4) & 1) << 3);
                int c = kk * 2 + ((lid >> 3) & 1);
                uint32_t bf[4];
                ldsm4(bf, s + 16384 + row * 128 + ((c ^ (row & 7)) << 4));
                #pragma unroll
                for (int mt = 0; mt < 2; ++mt) {
                    mma_f16(acc[mt][2 * p],     af[mt], bf);
                    mma_f16(acc[mt][2 * p + 1], af[mt], bf + 2);
                }
            }
        }
        __syncthreads();
    }

    #pragma unroll
    for (int mt = 0; mt < 2; ++mt) {
        int rbase = m0 + wm + mt * 16 + (lid >> 2);
        #pragma unroll
        for (int half = 0; half < 2; ++half) {
            int m = rbase + half * 8;
            if (m < M) {
                #pragma unroll
                for (int nt = 0; nt < 8; ++nt) {
                    int n = n0 + wn + nt * 8 + (lid & 3) * 2;
                    float2 o;
                    o.x = acc[mt][nt][half * 2 + 0];
                    o.y = acc[mt][nt][half * 2 + 1];
                    if (bias) { o.x += bias[n]; o.y += bias[n + 1]; }
                    if (relu) { o.x = fmaxf(o.x, 0.f); o.y = fmaxf(o.y, 0.f); }
                    if (C)
                        *reinterpret_cast<float2*>(C + (size_t)m * F + n) = o;
                    if (C16) {
                        __half2 h = __floats2half2_rn(o.x, o.y);
                        *reinterpret_cast<__half2*>(C16 + (size_t)m * F + n) = h;
                    }
                }
            }
        }
    }
}

// ==================== launcher ====================
extern "C" void kernel_launch(void* const* d_in, const int* in_sizes, int n_in,
                              void* d_out, int out_size) {
    const float* x   = (const float*)d_in[0];
    const float* W1  = (const float*)d_in[1];
    const float* b1  = (const float*)d_in[2];
    const float* W2  = (const float*)d_in[3];
    const float* b2  = (const float*)d_in[4];
    const float* W3  = (const float*)d_in[5];
    const float* b3  = (const float*)d_in[6];
    const int*   src = (const int*)d_in[7];
    const int*   dst = (const int*)d_in[8];

    float* out = (float*)d_out;
    float* h4 = out;
    float* h3 = out + (size_t)NN * F;
    float* h2 = out + 2 * (size_t)NN * F;

    void* ivec = nullptr;
    __half *x16 = nullptr, *hf16 = nullptr, *A16 = nullptr;
    __half *W1h = nullptr, *W2h = nullptr, *W3h = nullptr;
    cudaGetSymbolAddress(&ivec, g_ivec);
    cudaGetSymbolAddress((void**)&x16,  g_x16);
    cudaGetSymbolAddress((void**)&hf16, g_hf16);
    cudaGetSymbolAddress((void**)&A16,  g_A16);
    cudaGetSymbolAddress((void**)&W1h, g_W1h);
    cudaGetSymbolAddress((void**)&W2h, g_W2h);
    cudaGetSymbolAddress((void**)&W3h, g_W3h);

    cudaFuncSetAttribute(gemm_mma, cudaFuncAttributeMaxDynamicSharedMemorySize, GEMM_SMEM);

    // ONE side stream + two events (the R10-proven pattern; two streams leak)
    cudaStream_t s1;
    cudaStreamCreateWithFlags(&s1, cudaStreamNonBlocking);
    cudaEvent_t evFork, evY1;
    cudaEventCreateWithFlags(&evFork, cudaEventDisableTiming);
    cudaEventCreateWithFlags(&evY1, cudaEventDisableTiming);

    dim3 ggrid(4, (NN + 127) / 128);
    dim3 ggrid2(8, (NN + 127) / 128);

    // ---- side stream: x->fp16, W splits, Y1 = x16 @ W1 (CSR-independent) ----
    cudaEventRecord(evFork, 0);
    cudaStreamWaitEvent(s1, evFork, 0);
    xconvert_kernel<<<(NN * F / 4 + 255) / 256, 256, 0, s1>>>(x, x16);
    wsplit_kernel<<<dim3(16, 16, 1), dim3(32, 32), 0, s1>>>(W1, W1h, nullptr, nullptr);
    gemm_mma<<<ggrid, 256, GEMM_SMEM, s1>>>(x16, W1h, nullptr, nullptr, A16,
                                            nullptr, nullptr, nullptr, NN, 0, 0);
    wsplit_kernel<<<dim3(16, 16, 2), dim3(32, 32), 0, s1>>>(W2, W2h, W3, W3h);
    cudaEventRecord(evY1, s1);

    // ---- main stream: CSR build (hidden under the Y1 chain) ----
    cudaMemsetAsync(ivec, 0, sizeof(int) * 3 * NN, 0);
    degree_kernel<<<(NE / 4 + 255) / 256, 256>>>(src, dst);
    scan1_kernel<<<40, 256>>>();
    scan2_kernel<<<40, 256>>>();
    scatter_kernel<<<(NE / 2 + 255) / 256, 256>>>(src, dst);
    cudaStreamWaitEvent(0, evY1, 0);

    // layer 1: h1 = relu(Agg(Y1) + b1)     [linearity: Agg(X)W1 = Agg(X W1)]
    agg_kernel<<<NN / 2, 256>>>(A16, hf16, b1, 1);
    // layer 2: h2 = relu(Agg(h1) W2 + b2)  -> fp32 d_out + fp16 x16
    agg_kernel<<<NN / 2, 256>>>(hf16, A16, nullptr, 0);
    gemm_mma<<<ggrid, 256, GEMM_SMEM>>>(A16, W2h, b2, h2, x16,
                                        nullptr, nullptr, nullptr, NN, 1, 0);
    // layer 3: shared agg feeds h3 (W2,relu) + h4 (W3) in one dual GEMM
    agg_kernel<<<NN / 2, 256>>>(x16, A16, nullptr, 0);
    gemm_mma<<<ggrid2, 256, GEMM_SMEM>>>(A16, W2h, b2, h3, nullptr,
                                         W3h, b3, h4, NN, 1, 1);
}

// round 13
// speedup vs baseline: 1.0160x; 1.0160x over previous
#include <cuda_runtime.h>
#include <cuda_fp16.h>
#include <cstdint>

#define NN 10000
#define NE 160000
#define F 512

// ==================== scratch (device globals) ====================
__device__ int   g_ivec[3][NN];
#define g_deg_out (g_ivec[0])
#define g_deg_in  (g_ivec[1])
#define g_cnt     (g_ivec[2])
__device__ int   g_off[NN + 1];
__device__ int   g_bsum[40];
__device__ int   g_csr_src[NE];
__device__ float g_csr_w[NE];
__device__ __half g_x16[(size_t)NN * F];    // fp16 x, later fp16 h2
__device__ __half g_hf16[(size_t)NN * F];   // fp16 h1
__device__ __half g_A16[(size_t)NN * F];    // Y1, then aggregated GEMM A operand
__device__ __half g_W1h[F * F], g_W2h[F * F], g_W3h[F * F];

// ==================== PTX helpers ====================
__device__ __forceinline__ uint32_t smem_to_u32(const void* p) {
    uint32_t a;
    asm("{ .reg .u64 t; cvta.to.shared.u64 t, %1; cvt.u32.u64 %0, t; }" : "=r"(a) : "l"(p));
    return a;
}
__device__ __forceinline__ void cp_async16(uint32_t dst, const void* src, int sz) {
    asm volatile("cp.async.cg.shared.global [%0], [%1], 16, %2;"
        :: "r"(dst), "l"(src), "r"(sz) : "memory");
}
__device__ __forceinline__ void ldsm4(uint32_t* r, uint32_t addr) {
    asm volatile("ldmatrix.sync.aligned.m8n8.x4.shared.b16 {%0,%1,%2,%3}, [%4];"
        : "=r"(r[0]), "=r"(r[1]), "=r"(r[2]), "=r"(r[3]) : "r"(addr));
}
__device__ __forceinline__ void mma_f16(float* d, const uint32_t* a, const uint32_t* b) {
    asm volatile(
        "mma.sync.aligned.m16n8k16.row.col.f32.f16.f16.f32 "
        "{%0,%1,%2,%3}, {%4,%5,%6,%7}, {%8,%9}, {%0,%1,%2,%3};"
        : "+f"(d[0]), "+f"(d[1]), "+f"(d[2]), "+f"(d[3])
        : "r"(a[0]), "r"(a[1]), "r"(a[2]), "r"(a[3]), "r"(b[0]), "r"(b[1]));
}

// ==================== setup kernels ====================
__global__ void degree_kernel(const int* __restrict__ src, const int* __restrict__ dst) {
    int i = blockIdx.x * blockDim.x + threadIdx.x;   // int4 index
    if (i < NE / 4) {
        int4 s = reinterpret_cast<const int4*>(src)[i];
        int4 d = reinterpret_cast<const int4*>(dst)[i];
        atomicAdd(&g_deg_out[s.x], 1); atomicAdd(&g_deg_out[s.y], 1);
        atomicAdd(&g_deg_out[s.z], 1); atomicAdd(&g_deg_out[s.w], 1);
        atomicAdd(&g_deg_in[d.x], 1);  atomicAdd(&g_deg_in[d.y], 1);
        atomicAdd(&g_deg_in[d.z], 1);  atomicAdd(&g_deg_in[d.w], 1);
    }
}

__global__ void scan1_kernel() {
    __shared__ int wsum[8];
    int tid = threadIdx.x;
    int idx = blockIdx.x * 256 + tid;
    int v = (idx < NN) ? g_deg_in[idx] : 0;
    int x = v;
    #pragma unroll
    for (int d = 1; d < 32; d <<= 1) {
        int y = __shfl_up_sync(0xffffffffu, x, d);
        if ((tid & 31) >= d) x += y;
    }
    if ((tid & 31) == 31) wsum[tid >> 5] = x;
    __syncthreads();
    if (tid < 8) {
        int w = wsum[tid];
        #pragma unroll
        for (int d = 1; d < 8; d <<= 1) {
            int y = __shfl_up_sync(0xffu, w, d);
            if (tid >= d) w += y;
        }
        wsum[tid] = w;
    }
    __syncthreads();
    int incl = x + ((tid >= 32) ? wsum[(tid >> 5) - 1] : 0);
    if (idx <= NN) g_off[idx] = incl - v;
    if (tid == 255) g_bsum[blockIdx.x] = incl;
}

__global__ void scan2_kernel() {
    __shared__ int pref[41];
    int tid = threadIdx.x;
    if (tid == 0) {
        int s = 0;
        #pragma unroll
        for (int b = 0; b < 40; ++b) { pref[b] = s; s += g_bsum[b]; }
        pref[40] = s;
    }
    __syncthreads();
    int idx = blockIdx.x * 256 + tid;
    if (idx < NN) g_off[idx] += pref[blockIdx.x];
    if (idx == NN - 1) g_off[NN] = pref[40];
}

__global__ void scatter_kernel(const int* __restrict__ src, const int* __restrict__ dst) {
    int i = blockIdx.x * blockDim.x + threadIdx.x;
    if (i < NE / 2) {
        int2 s2 = reinterpret_cast<const int2*>(src)[i];
        int2 d2 = reinterpret_cast<const int2*>(dst)[i];
        int p0 = g_off[d2.x] + atomicAdd(&g_cnt[d2.x], 1);
        g_csr_src[p0] = s2.x;
        g_csr_w[p0]   = rsqrtf((float)g_deg_out[s2.x]);
        int p1 = g_off[d2.y] + atomicAdd(&g_cnt[d2.y], 1);
        g_csr_src[p1] = s2.y;
        g_csr_w[p1]   = rsqrtf((float)g_deg_out[s2.y]);
    }
}

// x fp32 -> fp16
__global__ void xconvert_kernel(const float* __restrict__ x, __half* __restrict__ o) {
    int i = blockIdx.x * blockDim.x + threadIdx.x;
    float4 v = reinterpret_cast<const float4*>(x)[i];
    __half2 a = __floats2half2_rn(v.x, v.y);
    __half2 b = __floats2half2_rn(v.z, v.w);
    uint32_t ua = *reinterpret_cast<uint32_t*>(&a);
    uint32_t ub = *reinterpret_cast<uint32_t*>(&b);
    reinterpret_cast<uint2*>(o)[i] = make_uint2(ua, ub);
}

// W k-major -> transposed fp16 Wt[n][k]; grid.z picks subset
__global__ void wsplit_kernel(const float* __restrict__ Wa, __half* __restrict__ Oa,
                              const float* __restrict__ Wb, __half* __restrict__ Ob) {
    const float* W = (blockIdx.z == 0) ? Wa : Wb;
    __half* Oh = (blockIdx.z == 0) ? Oa : Ob;
    __shared__ float t[32][33];
    int n = blockIdx.x * 32 + threadIdx.x;
    int k = blockIdx.y * 32 + threadIdx.y;
    t[threadIdx.y][threadIdx.x] = W[(size_t)k * F + n];
    __syncthreads();
    int on = blockIdx.x * 32 + threadIdx.y;
    int ok = blockIdx.y * 32 + threadIdx.x;
    Oh[(size_t)on * F + ok] = __float2half_rn(t[threadIdx.x][threadIdx.y]);
}

// ==================== aggregation: 2 nodes per CTA (256 thr) ====================
__global__ __launch_bounds__(256) void agg_kernel(const __half* __restrict__ x,
                                                  __half* __restrict__ o,
                                                  const float* __restrict__ bias,
                                                  int relu) {
    int node = blockIdx.x * 2 + (threadIdx.x >> 7);
    int tid  = threadIdx.x & 127;
    if (node >= NN) return;
    int beg = g_off[node];
    int end = g_off[node + 1];
    const uint2* x2 = reinterpret_cast<const uint2*>(x);
    float4 acc = make_float4(0.f, 0.f, 0.f, 0.f);
    int i = beg;
    for (; i + 4 <= end; i += 4) {
        int   s0 = __ldg(&g_csr_src[i + 0]);
        int   s1 = __ldg(&g_csr_src[i + 1]);
        int   s2 = __ldg(&g_csr_src[i + 2]);
        int   s3 = __ldg(&g_csr_src[i + 3]);
        float w0 = __ldg(&g_csr_w[i + 0]);
        float w1 = __ldg(&g_csr_w[i + 1]);
        float w2 = __ldg(&g_csr_w[i + 2]);
        float w3 = __ldg(&g_csr_w[i + 3]);
        uint2 u0 = x2[(size_t)s0 * 128 + tid];
        uint2 u1 = x2[(size_t)s1 * 128 + tid];
        uint2 u2 = x2[(size_t)s2 * 128 + tid];
        uint2 u3 = x2[(size_t)s3 * 128 + tid];
        float2 a0 = __half22float2(*reinterpret_cast<__half2*>(&u0.x));
        float2 b0 = __half22float2(*reinterpret_cast<__half2*>(&u0.y));
        float2 a1 = __half22float2(*reinterpret_cast<__half2*>(&u1.x));
        float2 b1 = __half22float2(*reinterpret_cast<__half2*>(&u1.y));
        float2 a2 = __half22float2(*reinterpret_cast<__half2*>(&u2.x));
        float2 b2 = __half22float2(*reinterpret_cast<__half2*>(&u2.y));
        float2 a3 = __half22float2(*reinterpret_cast<__half2*>(&u3.x));
        float2 b3 = __half22float2(*reinterpret_cast<__half2*>(&u3.y));
        acc.x = fmaf(w0, a0.x, acc.x); acc.y = fmaf(w0, a0.y, acc.y);
        acc.z = fmaf(w0, b0.x, acc.z); acc.w = fmaf(w0, b0.y, acc.w);
        acc.x = fmaf(w1, a1.x, acc.x); acc.y = fmaf(w1, a1.y, acc.y);
        acc.z = fmaf(w1, b1.x, acc.z); acc.w = fmaf(w1, b1.y, acc.w);
        acc.x = fmaf(w2, a2.x, acc.x); acc.y = fmaf(w2, a2.y, acc.y);
        acc.z = fmaf(w2, b2.x, acc.z); acc.w = fmaf(w2, b2.y, acc.w);
        acc.x = fmaf(w3, a3.x, acc.x); acc.y = fmaf(w3, a3.y, acc.y);
        acc.z = fmaf(w3, b3.x, acc.z); acc.w = fmaf(w3, b3.y, acc.w);
    }
    for (; i < end; ++i) {
        int   s = __ldg(&g_csr_src[i]);
        float w = __ldg(&g_csr_w[i]);
        uint2 u = x2[(size_t)s * 128 + tid];
        float2 a = __half22float2(*reinterpret_cast<__half2*>(&u.x));
        float2 b = __half22float2(*reinterpret_cast<__half2*>(&u.y));
        acc.x = fmaf(w, a.x, acc.x); acc.y = fmaf(w, a.y, acc.y);
        acc.z = fmaf(w, b.x, acc.z); acc.w = fmaf(w, b.y, acc.w);
    }
    float ni = (end > beg) ? rsqrtf((float)(end - beg)) : 0.f;
    float r0 = acc.x * ni, r1 = acc.y * ni, r2 = acc.z * ni, r3 = acc.w * ni;
    if (bias) {
        float4 bv = reinterpret_cast<const float4*>(bias)[tid];
        r0 += bv.x; r1 += bv.y; r2 += bv.z; r3 += bv.w;
    }
    if (relu) {
        r0 = fmaxf(r0, 0.f); r1 = fmaxf(r1, 0.f);
        r2 = fmaxf(r2, 0.f); r3 = fmaxf(r3, 0.f);
    }
    __half2 p0 = __floats2half2_rn(r0, r1);
    __half2 p1 = __floats2half2_rn(r2, r3);
    uint2 u = make_uint2(*reinterpret_cast<uint32_t*>(&p0), *reinterpret_cast<uint32_t*>(&p1));
    reinterpret_cast<uint2*>(o + (size_t)node * F)[tid] = u;
}

// ==================== mma.sync GEMM: C = A@B^T (+bias, +relu) ====================
#define STAGE_BYTES 32768
#define NSTAGE 3
#define GEMM_SMEM (NSTAGE * STAGE_BYTES)

__device__ __forceinline__ void load_stage(
    uint32_t s, int m0, int n0, int M, int k0, int tid,
    const __half* __restrict__ A, const __half* __restrict__ B)
{
    #pragma unroll
    for (int i = 0; i < 4; ++i) {
        int v = tid + i * 256;
        int row = v >> 3, c = v & 7;
        uint32_t phys = (uint32_t)(row * 128 + ((c ^ (row & 7)) << 4));
        size_t gA = (size_t)(m0 + row) * F + k0 + c * 8;
        int sz = (m0 + row < M) ? 16 : 0;
        cp_async16(s + phys, A + gA, sz);
        size_t gB = (size_t)(n0 + row) * F + k0 + c * 8;
        cp_async16(s + 16384 + phys, B + gB, 16);
    }
    asm volatile("cp.async.commit_group;" ::: "memory");
}

__global__ __launch_bounds__(256, 2) void gemm_mma(
    const __half* __restrict__ A,
    const __half* __restrict__ B, const float* __restrict__ bias,
    float* __restrict__ C, __half* __restrict__ C16,
    const __half* __restrict__ B2, const float* __restrict__ bias2, float* __restrict__ C2,
    int M, int relu, int dual)
{
    extern __shared__ char smem[];
    const uint32_t sb = smem_to_u32(smem);
    const int tid = threadIdx.x;
    const int wid = tid >> 5, lid = tid & 31;
    int nb = blockIdx.x;
    if (dual && nb >= 4) {
        nb -= 4;
        B = B2; bias = bias2; C = C2; C16 = nullptr; relu = 0;
    }
    const int m0 = blockIdx.y * 128, n0 = nb * 128;
    const int wm = (wid & 3) * 32;
    const int wn = (wid >> 2) * 64;

    float acc[2][8][4];
    #pragma unroll
    for (int a = 0; a < 2; ++a)
        #pragma unroll
        for (int b = 0; b < 8; ++b)
            #pragma unroll
            for (int c = 0; c < 4; ++c) acc[a][b][c] = 0.f;

    load_stage(sb, m0, n0, M, 0, tid, A, B);
    load_stage(sb + STAGE_BYTES, m0, n0, M, 64, tid, A, B);

    const int NCH = F / 64;   // 8
    for (int ch = 0; ch < NCH; ++ch) {
        asm volatile("cp.async.wait_group 1;" ::: "memory");
        __syncthreads();
        if (ch + 2 < NCH)
            load_stage(sb + ((ch + 2) % NSTAGE) * STAGE_BYTES, m0, n0, M, (ch + 2) * 64, tid, A, B);
        else
            asm volatile("cp.async.commit_group;" ::: "memory");

        const uint32_t s = sb + (ch % NSTAGE) * STAGE_BYTES;
        #pragma unroll
        for (int kk = 0; kk < 4; ++kk) {
            uint32_t af[2][4];
            #pragma unroll
            for (int mt = 0; mt < 2; ++mt) {
                int row = wm + mt * 16 + (lid & 15);
                int c = kk * 2 + ((lid >> 4) & 1);
                ldsm4(af[mt], s + row * 128 + ((c ^ (row & 7)) << 4));
            }
            #pragma unroll
            for (int p = 0; p < 4; ++p) {
                int row = wn + p * 16 + (lid & 7) + (((lid >> 4) & 1) << 3);
                int c = kk * 2 + ((lid >> 3) & 1);
                uint32_t bf[4];
                ldsm4(bf, s + 16384 + row * 128 + ((c ^ (row & 7)) << 4));
                #pragma unroll
                for (int mt = 0; mt < 2; ++mt) {
                    mma_f16(acc[mt][2 * p],     af[mt], bf);
                    mma_f16(acc[mt][2 * p + 1], af[mt], bf + 2);
                }
            }
        }
        __syncthreads();
    }

    #pragma unroll
    for (int mt = 0; mt < 2; ++mt) {
        int rbase = m0 + wm + mt * 16 + (lid >> 2);
        #pragma unroll
        for (int half = 0; half < 2; ++half) {
            int m = rbase + half * 8;
            if (m < M) {
                #pragma unroll
                for (int nt = 0; nt < 8; ++nt) {
                    int n = n0 + wn + nt * 8 + (lid & 3) * 2;
                    float2 o;
                    o.x = acc[mt][nt][half * 2 + 0];
                    o.y = acc[mt][nt][half * 2 + 1];
                    if (bias) { o.x += bias[n]; o.y += bias[n + 1]; }
                    if (relu) { o.x = fmaxf(o.x, 0.f); o.y = fmaxf(o.y, 0.f); }
                    if (C)
                        *reinterpret_cast<float2*>(C + (size_t)m * F + n) = o;
                    if (C16) {
                        __half2 h = __floats2half2_rn(o.x, o.y);
                        *reinterpret_cast<__half2*>(C16 + (size_t)m * F + n) = h;
                    }
                }
            }
        }
    }
}

// ==================== launcher ====================
extern "C" void kernel_launch(void* const* d_in, const int* in_sizes, int n_in,
                              void* d_out, int out_size) {
    const float* x   = (const float*)d_in[0];
    const float* W1  = (const float*)d_in[1];
    const float* b1  = (const float*)d_in[2];
    const float* W2  = (const float*)d_in[3];
    const float* b2  = (const float*)d_in[4];
    const float* W3  = (const float*)d_in[5];
    const float* b3  = (const float*)d_in[6];
    const int*   src = (const int*)d_in[7];
    const int*   dst = (const int*)d_in[8];

    float* out = (float*)d_out;
    float* h4 = out;
    float* h3 = out + (size_t)NN * F;
    float* h2 = out + 2 * (size_t)NN * F;

    void* ivec = nullptr;
    __half *x16 = nullptr, *hf16 = nullptr, *A16 = nullptr;
    __half *W1h = nullptr, *W2h = nullptr, *W3h = nullptr;
    cudaGetSymbolAddress(&ivec, g_ivec);
    cudaGetSymbolAddress((void**)&x16,  g_x16);
    cudaGetSymbolAddress((void**)&hf16, g_hf16);
    cudaGetSymbolAddress((void**)&A16,  g_A16);
    cudaGetSymbolAddress((void**)&W1h, g_W1h);
    cudaGetSymbolAddress((void**)&W2h, g_W2h);
    cudaGetSymbolAddress((void**)&W3h, g_W3h);

    cudaFuncSetAttribute(gemm_mma, cudaFuncAttributeMaxDynamicSharedMemorySize, GEMM_SMEM);

    // ONE side stream (proven safe); three events
    cudaStream_t s1;
    cudaStreamCreateWithFlags(&s1, cudaStreamNonBlocking);
    cudaEvent_t evFork, evY1, evW23;
    cudaEventCreateWithFlags(&evFork, cudaEventDisableTiming);
    cudaEventCreateWithFlags(&evY1, cudaEventDisableTiming);
    cudaEventCreateWithFlags(&evW23, cudaEventDisableTiming);

    dim3 ggrid(4, (NN + 127) / 128);
    dim3 ggrid2(8, (NN + 127) / 128);

    // ---- side stream: xconv + W1 split + Y1 GEMM, THEN evY1; W2/W3 split after ----
    cudaEventRecord(evFork, 0);
    cudaStreamWaitEvent(s1, evFork, 0);
    xconvert_kernel<<<(NN * F / 4 + 255) / 256, 256, 0, s1>>>(x, x16);
    wsplit_kernel<<<dim3(16, 16, 1), dim3(32, 32), 0, s1>>>(W1, W1h, nullptr, nullptr);
    gemm_mma<<<ggrid, 256, GEMM_SMEM, s1>>>(x16, W1h, nullptr, nullptr, A16,
                                            nullptr, nullptr, nullptr, NN, 0, 0);
    cudaEventRecord(evY1, s1);                       // Y1 ready (critical)
    wsplit_kernel<<<dim3(16, 16, 2), dim3(32, 32), 0, s1>>>(W2, W2h, W3, W3h);
    cudaEventRecord(evW23, s1);                      // W2/W3 ready (hidden under aggs)

    // ---- main stream: CSR build (parallel with the Y1 chain) ----
    cudaMemsetAsync(ivec, 0, sizeof(int) * 3 * NN, 0);
    degree_kernel<<<(NE / 4 + 255) / 256, 256>>>(src, dst);
    scan1_kernel<<<40, 256>>>();
    scan2_kernel<<<40, 256>>>();
    scatter_kernel<<<(NE / 2 + 255) / 256, 256>>>(src, dst);
    cudaStreamWaitEvent(0, evY1, 0);

    // layer 1: h1 = relu(Agg(Y1) + b1)     [linearity: Agg(X)W1 = Agg(X W1)]
    agg_kernel<<<NN / 2, 256>>>(A16, hf16, b1, 1);
    // layer 2: h2 = relu(Agg(h1) W2 + b2)  -> fp32 d_out + fp16 x16
    agg_kernel<<<NN / 2, 256>>>(hf16, A16, nullptr, 0);
    cudaStreamWaitEvent(0, evW23, 0);                // W2/W3 certainly done by now
    gemm_mma<<<ggrid, 256, GEMM_SMEM>>>(A16, W2h, b2, h2, x16,
                                        nullptr, nullptr, nullptr, NN, 1, 0);
    // layer 3: shared agg feeds h3 (W2,relu) + h4 (W3) in one dual GEMM
    agg_kernel<<<NN / 2, 256>>>(x16, A16, nullptr, 0);
    gemm_mma<<<ggrid2, 256, GEMM_SMEM>>>(A16, W2h, b2, h3, nullptr,
                                         W3h, b3, h4, NN, 1, 1);
}

// round 14
// speedup vs baseline: 1.0277x; 1.0116x over previous
#include <cuda_runtime.h>
#include <cuda_fp16.h>
#include <cstdint>

#define NN 10000
#define NE 160000
#define F 512

// ==================== scratch (device globals) ====================
__device__ int   g_ivec[3][NN];
#define g_deg_out (g_ivec[0])
#define g_deg_in  (g_ivec[1])
#define g_cnt     (g_ivec[2])
__device__ int   g_off[NN + 1];
__device__ int   g_bsum[40];
__device__ int   g_csr_src[NE];
__device__ float g_csr_w[NE];
__device__ __half g_x16[(size_t)NN * F];    // fp16 x, later fp16 h2
__device__ __half g_hf16[(size_t)NN * F];   // fp16 h1
__device__ __half g_A16[(size_t)NN * F];    // Y1, then aggregated GEMM A operand
__device__ __half g_W1h[F * F], g_W2h[F * F], g_W3h[F * F];

// ==================== PTX helpers ====================
__device__ __forceinline__ uint32_t smem_to_u32(const void* p) {
    uint32_t a;
    asm("{ .reg .u64 t; cvta.to.shared.u64 t, %1; cvt.u32.u64 %0, t; }" : "=r"(a) : "l"(p));
    return a;
}
__device__ __forceinline__ void cp_async16(uint32_t dst, const void* src, int sz) {
    asm volatile("cp.async.cg.shared.global [%0], [%1], 16, %2;"
        :: "r"(dst), "l"(src), "r"(sz) : "memory");
}
__device__ __forceinline__ void ldsm4(uint32_t* r, uint32_t addr) {
    asm volatile("ldmatrix.sync.aligned.m8n8.x4.shared.b16 {%0,%1,%2,%3}, [%4];"
        : "=r"(r[0]), "=r"(r[1]), "=r"(r[2]), "=r"(r[3]) : "r"(addr));
}
__device__ __forceinline__ void mma_f16(float* d, const uint32_t* a, const uint32_t* b) {
    asm volatile(
        "mma.sync.aligned.m16n8k16.row.col.f32.f16.f16.f32 "
        "{%0,%1,%2,%3}, {%4,%5,%6,%7}, {%8,%9}, {%0,%1,%2,%3};"
        : "+f"(d[0]), "+f"(d[1]), "+f"(d[2]), "+f"(d[3])
        : "r"(a[0]), "r"(a[1]), "r"(a[2]), "r"(a[3]), "r"(b[0]), "r"(b[1]));
}

// ==================== setup kernels ====================
__global__ void degree_kernel(const int* __restrict__ src, const int* __restrict__ dst) {
    int e = blockIdx.x * blockDim.x + threadIdx.x;
    if (e < NE) {
        atomicAdd(&g_deg_out[src[e]], 1);
        atomicAdd(&g_deg_in[dst[e]], 1);
    }
}

__global__ void scan1_kernel() {
    __shared__ int wsum[8];
    int tid = threadIdx.x;
    int idx = blockIdx.x * 256 + tid;
    int v = (idx < NN) ? g_deg_in[idx] : 0;
    int x = v;
    #pragma unroll
    for (int d = 1; d < 32; d <<= 1) {
        int y = __shfl_up_sync(0xffffffffu, x, d);
        if ((tid & 31) >= d) x += y;
    }
    if ((tid & 31) == 31) wsum[tid >> 5] = x;
    __syncthreads();
    if (tid < 8) {
        int w = wsum[tid];
        #pragma unroll
        for (int d = 1; d < 8; d <<= 1) {
            int y = __shfl_up_sync(0xffu, w, d);
            if (tid >= d) w += y;
        }
        wsum[tid] = w;
    }
    __syncthreads();
    int incl = x + ((tid >= 32) ? wsum[(tid >> 5) - 1] : 0);
    if (idx <= NN) g_off[idx] = incl - v;
    if (tid == 255) g_bsum[blockIdx.x] = incl;
}

__global__ void scan2_kernel() {
    __shared__ int pref[41];
    int tid = threadIdx.x;
    if (tid == 0) {
        int s = 0;
        #pragma unroll
        for (int b = 0; b < 40; ++b) { pref[b] = s; s += g_bsum[b]; }
        pref[40] = s;
    }
    __syncthreads();
    int idx = blockIdx.x * 256 + tid;
    if (idx < NN) g_off[idx] += pref[blockIdx.x];
    if (idx == NN - 1) g_off[NN] = pref[40];
}

__global__ void scatter_kernel(const int* __restrict__ src, const int* __restrict__ dst) {
    int e = blockIdx.x * blockDim.x + threadIdx.x;
    if (e < NE) {
        int d = dst[e];
        int pos = g_off[d] + atomicAdd(&g_cnt[d], 1);
        int s = src[e];
        g_csr_src[pos] = s;
        g_csr_w[pos]   = rsqrtf((float)g_deg_out[s]);
    }
}

// x fp32 -> fp16
__global__ void xconvert_kernel(const float* __restrict__ x, __half* __restrict__ o) {
    int i = blockIdx.x * blockDim.x + threadIdx.x;
    float4 v = reinterpret_cast<const float4*>(x)[i];
    __half2 a = __floats2half2_rn(v.x, v.y);
    __half2 b = __floats2half2_rn(v.z, v.w);
    uint32_t ua = *reinterpret_cast<uint32_t*>(&a);
    uint32_t ub = *reinterpret_cast<uint32_t*>(&b);
    reinterpret_cast<uint2*>(o)[i] = make_uint2(ua, ub);
}

// W k-major -> transposed fp16 Wt[n][k]; grid.z picks subset
__global__ void wsplit_kernel(const float* __restrict__ Wa, __half* __restrict__ Oa,
                              const float* __restrict__ Wb, __half* __restrict__ Ob) {
    const float* W = (blockIdx.z == 0) ? Wa : Wb;
    __half* Oh = (blockIdx.z == 0) ? Oa : Ob;
    __shared__ float t[32][33];
    int n = blockIdx.x * 32 + threadIdx.x;
    int k = blockIdx.y * 32 + threadIdx.y;
    t[threadIdx.y][threadIdx.x] = W[(size_t)k * F + n];
    __syncthreads();
    int on = blockIdx.x * 32 + threadIdx.y;
    int ok = blockIdx.y * 32 + threadIdx.x;
    Oh[(size_t)on * F + ok] = __float2half_rn(t[threadIdx.x][threadIdx.y]);
}

// ==================== aggregation: one node per CTA (128 thr) ====================
__global__ __launch_bounds__(128) void agg_kernel(const __half* __restrict__ x,
                                                  __half* __restrict__ o,
                                                  const float* __restrict__ bias,
                                                  int relu) {
    int node = blockIdx.x;
    int tid  = threadIdx.x;
    int beg = g_off[node];
    int end = g_off[node + 1];
    const uint2* x2 = reinterpret_cast<const uint2*>(x);
    float4 acc = make_float4(0.f, 0.f, 0.f, 0.f);
    int i = beg;
    for (; i + 4 <= end; i += 4) {
        int   s0 = __ldg(&g_csr_src[i + 0]);
        int   s1 = __ldg(&g_csr_src[i + 1]);
        int   s2 = __ldg(&g_csr_src[i + 2]);
        int   s3 = __ldg(&g_csr_src[i + 3]);
        float w0 = __ldg(&g_csr_w[i + 0]);
        float w1 = __ldg(&g_csr_w[i + 1]);
        float w2 = __ldg(&g_csr_w[i + 2]);
        float w3 = __ldg(&g_csr_w[i + 3]);
        uint2 u0 = x2[(size_t)s0 * 128 + tid];
        uint2 u1 = x2[(size_t)s1 * 128 + tid];
        uint2 u2 = x2[(size_t)s2 * 128 + tid];
        uint2 u3 = x2[(size_t)s3 * 128 + tid];
        float2 a0 = __half22float2(*reinterpret_cast<__half2*>(&u0.x));
        float2 b0 = __half22float2(*reinterpret_cast<__half2*>(&u0.y));
        float2 a1 = __half22float2(*reinterpret_cast<__half2*>(&u1.x));
        float2 b1 = __half22float2(*reinterpret_cast<__half2*>(&u1.y));
        float2 a2 = __half22float2(*reinterpret_cast<__half2*>(&u2.x));
        float2 b2 = __half22float2(*reinterpret_cast<__half2*>(&u2.y));
        float2 a3 = __half22float2(*reinterpret_cast<__half2*>(&u3.x));
        float2 b3 = __half22float2(*reinterpret_cast<__half2*>(&u3.y));
        acc.x = fmaf(w0, a0.x, acc.x); acc.y = fmaf(w0, a0.y, acc.y);
        acc.z = fmaf(w0, b0.x, acc.z); acc.w = fmaf(w0, b0.y, acc.w);
        acc.x = fmaf(w1, a1.x, acc.x); acc.y = fmaf(w1, a1.y, acc.y);
        acc.z = fmaf(w1, b1.x, acc.z); acc.w = fmaf(w1, b1.y, acc.w);
        acc.x = fmaf(w2, a2.x, acc.x); acc.y = fmaf(w2, a2.y, acc.y);
        acc.z = fmaf(w2, b2.x, acc.z); acc.w = fmaf(w2, b2.y, acc.w);
        acc.x = fmaf(w3, a3.x, acc.x); acc.y = fmaf(w3, a3.y, acc.y);
        acc.z = fmaf(w3, b3.x, acc.z); acc.w = fmaf(w3, b3.y, acc.w);
    }
    for (; i < end; ++i) {
        int   s = __ldg(&g_csr_src[i]);
        float w = __ldg(&g_csr_w[i]);
        uint2 u = x2[(size_t)s * 128 + tid];
        float2 a = __half22float2(*reinterpret_cast<__half2*>(&u.x));
        float2 b = __half22float2(*reinterpret_cast<__half2*>(&u.y));
        acc.x = fmaf(w, a.x, acc.x); acc.y = fmaf(w, a.y, acc.y);
        acc.z = fmaf(w, b.x, acc.z); acc.w = fmaf(w, b.y, acc.w);
    }
    float ni = (end > beg) ? rsqrtf((float)(end - beg)) : 0.f;
    float r0 = acc.x * ni, r1 = acc.y * ni, r2 = acc.z * ni, r3 = acc.w * ni;
    if (bias) {
        float4 bv = reinterpret_cast<const float4*>(bias)[tid];
        r0 += bv.x; r1 += bv.y; r2 += bv.z; r3 += bv.w;
    }
    if (relu) {
        r0 = fmaxf(r0, 0.f); r1 = fmaxf(r1, 0.f);
        r2 = fmaxf(r2, 0.f); r3 = fmaxf(r3, 0.f);
    }
    __half2 p0 = __floats2half2_rn(r0, r1);
    __half2 p1 = __floats2half2_rn(r2, r3);
    uint2 u = make_uint2(*reinterpret_cast<uint32_t*>(&p0), *reinterpret_cast<uint32_t*>(&p1));
    reinterpret_cast<uint2*>(o + (size_t)node * F)[tid] = u;
}

// ==================== mma.sync GEMM: C = A@B^T (+bias, +relu) ====================
#define STAGE_BYTES 32768
#define NSTAGE 3
#define GEMM_SMEM (NSTAGE * STAGE_BYTES)

__device__ __forceinline__ void load_stage(
    uint32_t s, int m0, int n0, int M, int k0, int tid,
    const __half* __restrict__ A, const __half* __restrict__ B)
{
    #pragma unroll
    for (int i = 0; i < 4; ++i) {
        int v = tid + i * 256;
        int row = v >> 3, c = v & 7;
        uint32_t phys = (uint32_t)(row * 128 + ((c ^ (row & 7)) << 4));
        size_t gA = (size_t)(m0 + row) * F + k0 + c * 8;
        int sz = (m0 + row < M) ? 16 : 0;
        cp_async16(s + phys, A + gA, sz);
        size_t gB = (size_t)(n0 + row) * F + k0 + c * 8;
        cp_async16(s + 16384 + phys, B + gB, 16);
    }
    asm volatile("cp.async.commit_group;" ::: "memory");
}

__global__ __launch_bounds__(256, 2) void gemm_mma(
    const __half* __restrict__ A,
    const __half* __restrict__ B, const float* __restrict__ bias,
    float* __restrict__ C, __half* __restrict__ C16,
    const __half* __restrict__ B2, const float* __restrict__ bias2, float* __restrict__ C2,
    int M, int relu, int dual)
{
    extern __shared__ char smem[];
    const uint32_t sb = smem_to_u32(smem);
    const int tid = threadIdx.x;
    const int wid = tid >> 5, lid = tid & 31;
    int nb = blockIdx.x;
    if (dual && nb >= 4) {
        nb -= 4;
        B = B2; bias = bias2; C = C2; C16 = nullptr; relu = 0;
    }
    const int m0 = blockIdx.y * 128, n0 = nb * 128;
    const int wm = (wid & 3) * 32;
    const int wn = (wid >> 2) * 64;

    float acc[2][8][4];
    #pragma unroll
    for (int a = 0; a < 2; ++a)
        #pragma unroll
        for (int b = 0; b < 8; ++b)
            #pragma unroll
            for (int c = 0; c < 4; ++c) acc[a][b][c] = 0.f;

    load_stage(sb, m0, n0, M, 0, tid, A, B);
    load_stage(sb + STAGE_BYTES, m0, n0, M, 64, tid, A, B);

    const int NCH = F / 64;   // 8
    for (int ch = 0; ch < NCH; ++ch) {
        asm volatile("cp.async.wait_group 1;" ::: "memory");
        __syncthreads();
        if (ch + 2 < NCH)
            load_stage(sb + ((ch + 2) % NSTAGE) * STAGE_BYTES, m0, n0, M, (ch + 2) * 64, tid, A, B);
        else
            asm volatile("cp.async.commit_group;" ::: "memory");

        const uint32_t s = sb + (ch % NSTAGE) * STAGE_BYTES;
        #pragma unroll
        for (int kk = 0; kk < 4; ++kk) {
            uint32_t af[2][4];
            #pragma unroll
            for (int mt = 0; mt < 2; ++mt) {
                int row = wm + mt * 16 + (lid & 15);
                int c = kk * 2 + ((lid >> 4) & 1);
                ldsm4(af[mt], s + row * 128 + ((c ^ (row & 7)) << 4));
            }
            #pragma unroll
            for (int p = 0; p < 4; ++p) {
                int row = wn + p * 16 + (lid & 7) + (((lid >> 4) & 1) << 3);
                int c = kk * 2 + ((lid >> 3) & 1);
                uint32_t bf[4];
                ldsm4(bf, s + 16384 + row * 128 + ((c ^ (row & 7)) << 4));
                #pragma unroll
                for (int mt = 0; mt < 2; ++mt) {
                    mma_f16(acc[mt][2 * p],     af[mt], bf);
                    mma_f16(acc[mt][2 * p + 1], af[mt], bf + 2);
                }
            }
        }
        __syncthreads();
    }

    #pragma unroll
    for (int mt = 0; mt < 2; ++mt) {
        int rbase = m0 + wm + mt * 16 + (lid >> 2);
        #pragma unroll
        for (int half = 0; half < 2; ++half) {
            int m = rbase + half * 8;
            if (m < M) {
                #pragma unroll
                for (int nt = 0; nt < 8; ++nt) {
                    int n = n0 + wn + nt * 8 + (lid & 3) * 2;
                    float2 o;
                    o.x = acc[mt][nt][half * 2 + 0];
                    o.y = acc[mt][nt][half * 2 + 1];
                    if (bias) { o.x += bias[n]; o.y += bias[n + 1]; }
                    if (relu) { o.x = fmaxf(o.x, 0.f); o.y = fmaxf(o.y, 0.f); }
                    if (C)
                        *reinterpret_cast<float2*>(C + (size_t)m * F + n) = o;
                    if (C16) {
                        __half2 h = __floats2half2_rn(o.x, o.y);
                        *reinterpret_cast<__half2*>(C16 + (size_t)m * F + n) = h;
                    }
                }
            }
        }
    }
}

// ==================== launcher ====================
extern "C" void kernel_launch(void* const* d_in, const int* in_sizes, int n_in,
                              void* d_out, int out_size) {
    const float* x   = (const float*)d_in[0];
    const float* W1  = (const float*)d_in[1];
    const float* b1  = (const float*)d_in[2];
    const float* W2  = (const float*)d_in[3];
    const float* b2  = (const float*)d_in[4];
    const float* W3  = (const float*)d_in[5];
    const float* b3  = (const float*)d_in[6];
    const int*   src = (const int*)d_in[7];
    const int*   dst = (const int*)d_in[8];

    float* out = (float*)d_out;
    float* h4 = out;
    float* h3 = out + (size_t)NN * F;
    float* h2 = out + 2 * (size_t)NN * F;

    void* ivec = nullptr;
    __half *x16 = nullptr, *hf16 = nullptr, *A16 = nullptr;
    __half *W1h = nullptr, *W2h = nullptr, *W3h = nullptr;
    cudaGetSymbolAddress(&ivec, g_ivec);
    cudaGetSymbolAddress((void**)&x16,  g_x16);
    cudaGetSymbolAddress((void**)&hf16, g_hf16);
    cudaGetSymbolAddress((void**)&A16,  g_A16);
    cudaGetSymbolAddress((void**)&W1h, g_W1h);
    cudaGetSymbolAddress((void**)&W2h, g_W2h);
    cudaGetSymbolAddress((void**)&W3h, g_W3h);

    cudaFuncSetAttribute(gemm_mma, cudaFuncAttributeMaxDynamicSharedMemorySize, GEMM_SMEM);

    // ONE side stream (proven safe); three events
    cudaStream_t s1;
    cudaStreamCreateWithFlags(&s1, cudaStreamNonBlocking);
    cudaEvent_t evFork, evY1, evW23;
    cudaEventCreateWithFlags(&evFork, cudaEventDisableTiming);
    cudaEventCreateWithFlags(&evY1, cudaEventDisableTiming);
    cudaEventCreateWithFlags(&evW23, cudaEventDisableTiming);

    const int TB = 256;
    dim3 ggrid(4, (NN + 127) / 128);
    dim3 ggrid2(8, (NN + 127) / 128);

    // ---- side stream: xconv + W1 split + Y1 GEMM, THEN evY1; W2/W3 split after ----
    cudaEventRecord(evFork, 0);
    cudaStreamWaitEvent(s1, evFork, 0);
    xconvert_kernel<<<(NN * F / 4 + 255) / 256, 256, 0, s1>>>(x, x16);
    wsplit_kernel<<<dim3(16, 16, 1), dim3(32, 32), 0, s1>>>(W1, W1h, nullptr, nullptr);
    gemm_mma<<<ggrid, 256, GEMM_SMEM, s1>>>(x16, W1h, nullptr, nullptr, A16,
                                            nullptr, nullptr, nullptr, NN, 0, 0);
    cudaEventRecord(evY1, s1);                       // Y1 ready (critical)
    wsplit_kernel<<<dim3(16, 16, 2), dim3(32, 32), 0, s1>>>(W2, W2h, W3, W3h);
    cudaEventRecord(evW23, s1);                      // hidden under agg1+agg2

    // ---- main stream: CSR build (parallel with the Y1 chain) ----
    cudaMemsetAsync(ivec, 0, sizeof(int) * 3 * NN, 0);
    degree_kernel<<<(NE + TB - 1) / TB, TB>>>(src, dst);
    scan1_kernel<<<40, 256>>>();
    scan2_kernel<<<40, 256>>>();
    scatter_kernel<<<(NE + TB - 1) / TB, TB>>>(src, dst);
    cudaStreamWaitEvent(0, evY1, 0);

    // layer 1: h1 = relu(Agg(Y1) + b1)     [linearity: Agg(X)W1 = Agg(X W1)]
    agg_kernel<<<NN, 128>>>(A16, hf16, b1, 1);
    // layer 2: h2 = relu(Agg(h1) W2 + b2)  -> fp32 d_out + fp16 x16
    agg_kernel<<<NN, 128>>>(hf16, A16, nullptr, 0);
    cudaStreamWaitEvent(0, evW23, 0);
    gemm_mma<<<ggrid, 256, GEMM_SMEM>>>(A16, W2h, b2, h2, x16,
                                        nullptr, nullptr, nullptr, NN, 1, 0);
    // layer 3: shared agg feeds h3 (W2,relu) + h4 (W3) in one dual GEMM
    agg_kernel<<<NN, 128>>>(x16, A16, nullptr, 0);
    gemm_mma<<<ggrid2, 256, GEMM_SMEM>>>(A16, W2h, b2, h3, nullptr,
                                         W3h, b3, h4, NN, 1, 1);
}

// round 15
// speedup vs baseline: 1.0894x; 1.0601x over previous
#include <cuda_runtime.h>
#include <cuda_fp16.h>
#include <cstdint>

#define NN 10000
#define NE 160000
#define F 512

// ==================== scratch (device globals) ====================
__device__ int   g_ivec[3][NN];
#define g_deg_out (g_ivec[0])
#define g_deg_in  (g_ivec[1])
#define g_cnt     (g_ivec[2])
__device__ int   g_off[NN + 1];
__device__ int   g_bsum[40];
__device__ int   g_csr_src[NE];
__device__ float g_csr_w[NE];
__device__ __half g_x16[(size_t)NN * F];    // fp16 x, later fp16 h2
__device__ __half g_hf16[(size_t)NN * F];   // fp16 h1
__device__ __half g_A16[(size_t)NN * F];    // Y1, then aggregated GEMM A operand
__device__ __half g_W1h[F * F], g_W2h[F * F], g_W3h[F * F];

// ==================== PTX helpers ====================
__device__ __forceinline__ uint32_t smem_to_u32(const void* p) {
    uint32_t a;
    asm("{ .reg .u64 t; cvta.to.shared.u64 t, %1; cvt.u32.u64 %0, t; }" : "=r"(a) : "l"(p));
    return a;
}
__device__ __forceinline__ void cp_async16(uint32_t dst, const void* src, int sz) {
    asm volatile("cp.async.cg.shared.global [%0], [%1], 16, %2;"
        :: "r"(dst), "l"(src), "r"(sz) : "memory");
}
__device__ __forceinline__ void ldsm4(uint32_t* r, uint32_t addr) {
    asm volatile("ldmatrix.sync.aligned.m8n8.x4.shared.b16 {%0,%1,%2,%3}, [%4];"
        : "=r"(r[0]), "=r"(r[1]), "=r"(r[2]), "=r"(r[3]) : "r"(addr));
}
__device__ __forceinline__ void mma_f16(float* d, const uint32_t* a, const uint32_t* b) {
    asm volatile(
        "mma.sync.aligned.m16n8k16.row.col.f32.f16.f16.f32 "
        "{%0,%1,%2,%3}, {%4,%5,%6,%7}, {%8,%9}, {%0,%1,%2,%3};"
        : "+f"(d[0]), "+f"(d[1]), "+f"(d[2]), "+f"(d[3])
        : "r"(a[0]), "r"(a[1]), "r"(a[2]), "r"(a[3]), "r"(b[0]), "r"(b[1]));
}

// ==================== setup kernels ====================
__global__ void degree_kernel(const int* __restrict__ src, const int* __restrict__ dst) {
    int e = blockIdx.x * blockDim.x + threadIdx.x;
    if (e < NE) {
        atomicAdd(&g_deg_out[src[e]], 1);
        atomicAdd(&g_deg_in[dst[e]], 1);
    }
}

__global__ void scan1_kernel() {
    __shared__ int wsum[8];
    int tid = threadIdx.x;
    int idx = blockIdx.x * 256 + tid;
    int v = (idx < NN) ? g_deg_in[idx] : 0;
    int x = v;
    #pragma unroll
    for (int d = 1; d < 32; d <<= 1) {
        int y = __shfl_up_sync(0xffffffffu, x, d);
        if ((tid & 31) >= d) x += y;
    }
    if ((tid & 31) == 31) wsum[tid >> 5] = x;
    __syncthreads();
    if (tid < 8) {
        int w = wsum[tid];
        #pragma unroll
        for (int d = 1; d < 8; d <<= 1) {
            int y = __shfl_up_sync(0xffu, w, d);
            if (tid >= d) w += y;
        }
        wsum[tid] = w;
    }
    __syncthreads();
    int incl = x + ((tid >= 32) ? wsum[(tid >> 5) - 1] : 0);
    if (idx <= NN) g_off[idx] = incl - v;
    if (tid == 255) g_bsum[blockIdx.x] = incl;
}

__global__ void scan2_kernel() {
    __shared__ int pref[41];
    int tid = threadIdx.x;
    if (tid == 0) {
        int s = 0;
        #pragma unroll
        for (int b = 0; b < 40; ++b) { pref[b] = s; s += g_bsum[b]; }
        pref[40] = s;
    }
    __syncthreads();
    int idx = blockIdx.x * 256 + tid;
    if (idx < NN) g_off[idx] += pref[blockIdx.x];
    if (idx == NN - 1) g_off[NN] = pref[40];
}

__global__ void scatter_kernel(const int* __restrict__ src, const int* __restrict__ dst) {
    int e = blockIdx.x * blockDim.x + threadIdx.x;
    if (e < NE) {
        int d = dst[e];
        int pos = g_off[d] + atomicAdd(&g_cnt[d], 1);
        int s = src[e];
        g_csr_src[pos] = s;
        g_csr_w[pos]   = rsqrtf((float)g_deg_out[s]);
    }
}

// x fp32 -> fp16
__global__ void xconvert_kernel(const float* __restrict__ x, __half* __restrict__ o) {
    int i = blockIdx.x * blockDim.x + threadIdx.x;
    float4 v = reinterpret_cast<const float4*>(x)[i];
    __half2 a = __floats2half2_rn(v.x, v.y);
    __half2 b = __floats2half2_rn(v.z, v.w);
    uint32_t ua = *reinterpret_cast<uint32_t*>(&a);
    uint32_t ub = *reinterpret_cast<uint32_t*>(&b);
    reinterpret_cast<uint2*>(o)[i] = make_uint2(ua, ub);
}

// W k-major -> transposed fp16 Wt[n][k]; grid.z picks subset
__global__ void wsplit_kernel(const float* __restrict__ Wa, __half* __restrict__ Oa,
                              const float* __restrict__ Wb, __half* __restrict__ Ob) {
    const float* W = (blockIdx.z == 0) ? Wa : Wb;
    __half* Oh = (blockIdx.z == 0) ? Oa : Ob;
    __shared__ float t[32][33];
    int n = blockIdx.x * 32 + threadIdx.x;
    int k = blockIdx.y * 32 + threadIdx.y;
    t[threadIdx.y][threadIdx.x] = W[(size_t)k * F + n];
    __syncthreads();
    int on = blockIdx.x * 32 + threadIdx.y;
    int ok = blockIdx.y * 32 + threadIdx.x;
    Oh[(size_t)on * F + ok] = __float2half_rn(t[threadIdx.x][threadIdx.y]);
}

// ==================== aggregation: one node per CTA (128 thr) ====================
__global__ __launch_bounds__(128) void agg_kernel(const __half* __restrict__ x,
                                                  __half* __restrict__ o,
                                                  const float* __restrict__ bias,
                                                  int relu) {
    int node = blockIdx.x;
    int tid  = threadIdx.x;
    int beg = g_off[node];
    int end = g_off[node + 1];
    const uint2* x2 = reinterpret_cast<const uint2*>(x);
    float4 acc = make_float4(0.f, 0.f, 0.f, 0.f);
    int i = beg;
    for (; i + 4 <= end; i += 4) {
        int   s0 = __ldg(&g_csr_src[i + 0]);
        int   s1 = __ldg(&g_csr_src[i + 1]);
        int   s2 = __ldg(&g_csr_src[i + 2]);
        int   s3 = __ldg(&g_csr_src[i + 3]);
        float w0 = __ldg(&g_csr_w[i + 0]);
        float w1 = __ldg(&g_csr_w[i + 1]);
        float w2 = __ldg(&g_csr_w[i + 2]);
        float w3 = __ldg(&g_csr_w[i + 3]);
        uint2 u0 = x2[(size_t)s0 * 128 + tid];
        uint2 u1 = x2[(size_t)s1 * 128 + tid];
        uint2 u2 = x2[(size_t)s2 * 128 + tid];
        uint2 u3 = x2[(size_t)s3 * 128 + tid];
        float2 a0 = __half22float2(*reinterpret_cast<__half2*>(&u0.x));
        float2 b0 = __half22float2(*reinterpret_cast<__half2*>(&u0.y));
        float2 a1 = __half22float2(*reinterpret_cast<__half2*>(&u1.x));
        float2 b1 = __half22float2(*reinterpret_cast<__half2*>(&u1.y));
        float2 a2 = __half22float2(*reinterpret_cast<__half2*>(&u2.x));
        float2 b2 = __half22float2(*reinterpret_cast<__half2*>(&u2.y));
        float2 a3 = __half22float2(*reinterpret_cast<__half2*>(&u3.x));
        float2 b3 = __half22float2(*reinterpret_cast<__half2*>(&u3.y));
        acc.x = fmaf(w0, a0.x, acc.x); acc.y = fmaf(w0, a0.y, acc.y);
        acc.z = fmaf(w0, b0.x, acc.z); acc.w = fmaf(w0, b0.y, acc.w);
        acc.x = fmaf(w1, a1.x, acc.x); acc.y = fmaf(w1, a1.y, acc.y);
        acc.z = fmaf(w1, b1.x, acc.z); acc.w = fmaf(w1, b1.y, acc.w);
        acc.x = fmaf(w2, a2.x, acc.x); acc.y = fmaf(w2, a2.y, acc.y);
        acc.z = fmaf(w2, b2.x, acc.z); acc.w = fmaf(w2, b2.y, acc.w);
        acc.x = fmaf(w3, a3.x, acc.x); acc.y = fmaf(w3, a3.y, acc.y);
        acc.z = fmaf(w3, b3.x, acc.z); acc.w = fmaf(w3, b3.y, acc.w);
    }
    for (; i < end; ++i) {
        int   s = __ldg(&g_csr_src[i]);
        float w = __ldg(&g_csr_w[i]);
        uint2 u = x2[(size_t)s * 128 + tid];
        float2 a = __half22float2(*reinterpret_cast<__half2*>(&u.x));
        float2 b = __half22float2(*reinterpret_cast<__half2*>(&u.y));
        acc.x = fmaf(w, a.x, acc.x); acc.y = fmaf(w, a.y, acc.y);
        acc.z = fmaf(w, b.x, acc.z); acc.w = fmaf(w, b.y, acc.w);
    }
    float ni = (end > beg) ? rsqrtf((float)(end - beg)) : 0.f;
    float r0 = acc.x * ni, r1 = acc.y * ni, r2 = acc.z * ni, r3 = acc.w * ni;
    if (bias) {
        float4 bv = reinterpret_cast<const float4*>(bias)[tid];
        r0 += bv.x; r1 += bv.y; r2 += bv.z; r3 += bv.w;
    }
    if (relu) {
        r0 = fmaxf(r0, 0.f); r1 = fmaxf(r1, 0.f);
        r2 = fmaxf(r2, 0.f); r3 = fmaxf(r3, 0.f);
    }
    __half2 p0 = __floats2half2_rn(r0, r1);
    __half2 p1 = __floats2half2_rn(r2, r3);
    uint2 u = make_uint2(*reinterpret_cast<uint32_t*>(&p0), *reinterpret_cast<uint32_t*>(&p1));
    reinterpret_cast<uint2*>(o + (size_t)node * F)[tid] = u;
}

// ==================== mma.sync GEMM: tile 96x128, warp 48x32 (2x4 warps) ====================
// Stage (28KB): A 96x128B [0,12288) + B 128x128B [12288,28672). 3 stages.
// Grid: (512/128=4 [x2 if dual], ceil(10000/96)=105). Max per-SM work: 3 CTAs x 0.75.
#define TM 96
#define STAGE_BYTES 28672
#define NSTAGE 3
#define GEMM_SMEM (NSTAGE * STAGE_BYTES)

__device__ __forceinline__ void load_stage(
    uint32_t s, int m0, int n0, int M, int k0, int tid,
    const __half* __restrict__ A, const __half* __restrict__ B)
{
    #pragma unroll
    for (int i = 0; i < 3; ++i) {          // A: 96 rows x 8 chunks = 768 vectors
        int v = tid + i * 256;
        int row = v >> 3, c = v & 7;
        uint32_t phys = (uint32_t)(row * 128 + ((c ^ (row & 7)) << 4));
        size_t gA = (size_t)(m0 + row) * F + k0 + c * 8;
        int sz = (m0 + row < M) ? 16 : 0;
        cp_async16(s + phys, A + gA, sz);
    }
    #pragma unroll
    for (int i = 0; i < 4; ++i) {          // B: 128 rows x 8 chunks = 1024 vectors
        int v = tid + i * 256;
        int row = v >> 3, c = v & 7;
        uint32_t phys = (uint32_t)(row * 128 + ((c ^ (row & 7)) << 4));
        size_t gB = (size_t)(n0 + row) * F + k0 + c * 8;
        cp_async16(s + 12288 + phys, B + gB, 16);
    }
    asm volatile("cp.async.commit_group;" ::: "memory");
}

__global__ __launch_bounds__(256, 2) void gemm_mma(
    const __half* __restrict__ A,
    const __half* __restrict__ B, const float* __restrict__ bias,
    float* __restrict__ C, __half* __restrict__ C16,
    const __half* __restrict__ B2, const float* __restrict__ bias2, float* __restrict__ C2,
    int M, int relu, int dual)
{
    extern __shared__ char smem[];
    const uint32_t sb = smem_to_u32(smem);
    const int tid = threadIdx.x;
    const int wid = tid >> 5, lid = tid & 31;
    int nb = blockIdx.x;
    if (dual && nb >= 4) {
        nb -= 4;
        B = B2; bias = bias2; C = C2; C16 = nullptr; relu = 0;
    }
    const int m0 = blockIdx.y * TM, n0 = nb * 128;
    const int wm = (wid & 1) * 48;      // 2 warps in M, 48 rows each
    const int wn = (wid >> 1) * 32;     // 4 warps in N, 32 cols each

    float acc[3][4][4];
    #pragma unroll
    for (int a = 0; a < 3; ++a)
        #pragma unroll
        for (int b = 0; b < 4; ++b)
            #pragma unroll
            for (int c = 0; c < 4; ++c) acc[a][b][c] = 0.f;

    load_stage(sb, m0, n0, M, 0, tid, A, B);
    load_stage(sb + STAGE_BYTES, m0, n0, M, 64, tid, A, B);

    const int NCH = F / 64;   // 8
    for (int ch = 0; ch < NCH; ++ch) {
        asm volatile("cp.async.wait_group 1;" ::: "memory");
        __syncthreads();
        if (ch + 2 < NCH)
            load_stage(sb + ((ch + 2) % NSTAGE) * STAGE_BYTES, m0, n0, M, (ch + 2) * 64, tid, A, B);
        else
            asm volatile("cp.async.commit_group;" ::: "memory");

        const uint32_t s = sb + (ch % NSTAGE) * STAGE_BYTES;
        #pragma unroll
        for (int kk = 0; kk < 4; ++kk) {
            uint32_t af[3][4];
            #pragma unroll
            for (int mt = 0; mt < 3; ++mt) {
                int row = wm + mt * 16 + (lid & 15);
                int c = kk * 2 + ((lid >> 4) & 1);
                ldsm4(af[mt], s + row * 128 + ((c ^ (row & 7)) << 4));
            }
            #pragma unroll
            for (int p = 0; p < 2; ++p) {
                int row = wn + p * 16 + (lid & 7) + (((lid >> 4) & 1) << 3);
                int c = kk * 2 + ((lid >> 3) & 1);
                uint32_t bf[4];
                ldsm4(bf, s + 12288 + row * 128 + ((c ^ (row & 7)) << 4));
                #pragma unroll
                for (int mt = 0; mt < 3; ++mt) {
                    mma_f16(acc[mt][2 * p],     af[mt], bf);
                    mma_f16(acc[mt][2 * p + 1], af[mt], bf + 2);
                }
            }
        }
        __syncthreads();
    }

    #pragma unroll
    for (int mt = 0; mt < 3; ++mt) {
        int rbase = m0 + wm + mt * 16 + (lid >> 2);
        #pragma unroll
        for (int half = 0; half < 2; ++half) {
            int m = rbase + half * 8;
            if (m < M) {
                #pragma unroll
                for (int nt = 0; nt < 4; ++nt) {
                    int n = n0 + wn + nt * 8 + (lid & 3) * 2;
                    float2 o;
                    o.x = acc[mt][nt][half * 2 + 0];
                    o.y = acc[mt][nt][half * 2 + 1];
                    if (bias) { o.x += bias[n]; o.y += bias[n + 1]; }
                    if (relu) { o.x = fmaxf(o.x, 0.f); o.y = fmaxf(o.y, 0.f); }
                    if (C)
                        *reinterpret_cast<float2*>(C + (size_t)m * F + n) = o;
                    if (C16) {
                        __half2 h = __floats2half2_rn(o.x, o.y);
                        *reinterpret_cast<__half2*>(C16 + (size_t)m * F + n) = h;
                    }
                }
            }
        }
    }
}

// ==================== launcher ====================
extern "C" void kernel_launch(void* const* d_in, const int* in_sizes, int n_in,
                              void* d_out, int out_size) {
    const float* x   = (const float*)d_in[0];
    const float* W1  = (const float*)d_in[1];
    const float* b1  = (const float*)d_in[2];
    const float* W2  = (const float*)d_in[3];
    const float* b2  = (const float*)d_in[4];
    const float* W3  = (const float*)d_in[5];
    const float* b3  = (const float*)d_in[6];
    const int*   src = (const int*)d_in[7];
    const int*   dst = (const int*)d_in[8];

    float* out = (float*)d_out;
    float* h4 = out;
    float* h3 = out + (size_t)NN * F;
    float* h2 = out + 2 * (size_t)NN * F;

    void* ivec = nullptr;
    __half *x16 = nullptr, *hf16 = nullptr, *A16 = nullptr;
    __half *W1h = nullptr, *W2h = nullptr, *W3h = nullptr;
    cudaGetSymbolAddress(&ivec, g_ivec);
    cudaGetSymbolAddress((void**)&x16,  g_x16);
    cudaGetSymbolAddress((void**)&hf16, g_hf16);
    cudaGetSymbolAddress((void**)&A16,  g_A16);
    cudaGetSymbolAddress((void**)&W1h, g_W1h);
    cudaGetSymbolAddress((void**)&W2h, g_W2h);
    cudaGetSymbolAddress((void**)&W3h, g_W3h);

    cudaFuncSetAttribute(gemm_mma, cudaFuncAttributeMaxDynamicSharedMemorySize, GEMM_SMEM);

    // ONE side stream (proven safe); three events
    cudaStream_t s1;
    cudaStreamCreateWithFlags(&s1, cudaStreamNonBlocking);
    cudaEvent_t evFork, evY1, evW23;
    cudaEventCreateWithFlags(&evFork, cudaEventDisableTiming);
    cudaEventCreateWithFlags(&evY1, cudaEventDisableTiming);
    cudaEventCreateWithFlags(&evW23, cudaEventDisableTiming);

    const int TB = 256;
    const int MB = (NN + TM - 1) / TM;   // 105 M-blocks
    dim3 ggrid(4, MB);
    dim3 ggrid2(8, MB);

    // ---- side stream: xconv + W1 split + Y1 GEMM, THEN evY1; W2/W3 split after ----
    cudaEventRecord(evFork, 0);
    cudaStreamWaitEvent(s1, evFork, 0);
    xconvert_kernel<<<(NN * F / 4 + 255) / 256, 256, 0, s1>>>(x, x16);
    wsplit_kernel<<<dim3(16, 16, 1), dim3(32, 32), 0, s1>>>(W1, W1h, nullptr, nullptr);
    gemm_mma<<<ggrid, 256, GEMM_SMEM, s1>>>(x16, W1h, nullptr, nullptr, A16,
                                            nullptr, nullptr, nullptr, NN, 0, 0);
    cudaEventRecord(evY1, s1);                       // Y1 ready (critical)
    wsplit_kernel<<<dim3(16, 16, 2), dim3(32, 32), 0, s1>>>(W2, W2h, W3, W3h);
    cudaEventRecord(evW23, s1);                      // hidden under agg1+agg2

    // ---- main stream: CSR build (parallel with the Y1 chain) ----
    cudaMemsetAsync(ivec, 0, sizeof(int) * 3 * NN, 0);
    degree_kernel<<<(NE + TB - 1) / TB, TB>>>(src, dst);
    scan1_kernel<<<40, 256>>>();
    scan2_kernel<<<40, 256>>>();
    scatter_kernel<<<(NE + TB - 1) / TB, TB>>>(src, dst);
    cudaStreamWaitEvent(0, evY1, 0);

    // layer 1: h1 = relu(Agg(Y1) + b1)     [linearity: Agg(X)W1 = Agg(X W1)]
    agg_kernel<<<NN, 128>>>(A16, hf16, b1, 1);
    // layer 2: h2 = relu(Agg(h1) W2 + b2)  -> fp32 d_out + fp16 x16
    agg_kernel<<<NN, 128>>>(hf16, A16, nullptr, 0);
    cudaStreamWaitEvent(0, evW23, 0);
    gemm_mma<<<ggrid, 256, GEMM_SMEM>>>(A16, W2h, b2, h2, x16,
                                        nullptr, nullptr, nullptr, NN, 1, 0);
    // layer 3: shared agg feeds h3 (W2,relu) + h4 (W3) in one dual GEMM
    agg_kernel<<<NN, 128>>>(x16, A16, nullptr, 0);
    gemm_mma<<<ggrid2, 256, GEMM_SMEM>>>(A16, W2h, b2, h3, nullptr,
                                         W3h, b3, h4, NN, 1, 1);
}

// round 16
// speedup vs baseline: 1.0934x; 1.0036x over previous
#include <cuda_runtime.h>
#include <cuda_fp16.h>
#include <cstdint>

#define NN 10000
#define NE 160000
#define F 512

// ==================== scratch (device globals) ====================
__device__ int   g_ivec[3][NN];
#define g_deg_out (g_ivec[0])
#define g_deg_in  (g_ivec[1])
#define g_cnt     (g_ivec[2])
__device__ int   g_off[NN + 1];
__device__ int   g_bsum[40];
__device__ int   g_csr_src[NE];
__device__ float g_csr_w[NE];
__device__ __half g_x16[(size_t)NN * F];    // fp16 x, later fp16 h2
__device__ __half g_hf16[(size_t)NN * F];   // fp16 h1
__device__ __half g_A16[(size_t)NN * F];    // Y1, then aggregated GEMM A operand
__device__ __half g_W1h[F * F], g_W2h[F * F], g_W3h[F * F];

// ==================== PTX helpers ====================
__device__ __forceinline__ uint32_t smem_to_u32(const void* p) {
    uint32_t a;
    asm("{ .reg .u64 t; cvta.to.shared.u64 t, %1; cvt.u32.u64 %0, t; }" : "=r"(a) : "l"(p));
    return a;
}
__device__ __forceinline__ void cp_async16(uint32_t dst, const void* src, int sz) {
    asm volatile("cp.async.cg.shared.global [%0], [%1], 16, %2;"
        :: "r"(dst), "l"(src), "r"(sz) : "memory");
}
__device__ __forceinline__ void ldsm4(uint32_t* r, uint32_t addr) {
    asm volatile("ldmatrix.sync.aligned.m8n8.x4.shared.b16 {%0,%1,%2,%3}, [%4];"
        : "=r"(r[0]), "=r"(r[1]), "=r"(r[2]), "=r"(r[3]) : "r"(addr));
}
__device__ __forceinline__ void mma_f16(float* d, const uint32_t* a, const uint32_t* b) {
    asm volatile(
        "mma.sync.aligned.m16n8k16.row.col.f32.f16.f16.f32 "
        "{%0,%1,%2,%3}, {%4,%5,%6,%7}, {%8,%9}, {%0,%1,%2,%3};"
        : "+f"(d[0]), "+f"(d[1]), "+f"(d[2]), "+f"(d[3])
        : "r"(a[0]), "r"(a[1]), "r"(a[2]), "r"(a[3]), "r"(b[0]), "r"(b[1]));
}

// ==================== setup kernels ====================
__global__ void degree_kernel(const int* __restrict__ src, const int* __restrict__ dst) {
    int e = blockIdx.x * blockDim.x + threadIdx.x;
    if (e < NE) {
        atomicAdd(&g_deg_out[src[e]], 1);
        atomicAdd(&g_deg_in[dst[e]], 1);
    }
}

__global__ void scan1_kernel() {
    __shared__ int wsum[8];
    int tid = threadIdx.x;
    int idx = blockIdx.x * 256 + tid;
    int v = (idx < NN) ? g_deg_in[idx] : 0;
    int x = v;
    #pragma unroll
    for (int d = 1; d < 32; d <<= 1) {
        int y = __shfl_up_sync(0xffffffffu, x, d);
        if ((tid & 31) >= d) x += y;
    }
    if ((tid & 31) == 31) wsum[tid >> 5] = x;
    __syncthreads();
    if (tid < 8) {
        int w = wsum[tid];
        #pragma unroll
        for (int d = 1; d < 8; d <<= 1) {
            int y = __shfl_up_sync(0xffu, w, d);
            if (tid >= d) w += y;
        }
        wsum[tid] = w;
    }
    __syncthreads();
    int incl = x + ((tid >= 32) ? wsum[(tid >> 5) - 1] : 0);
    if (idx <= NN) g_off[idx] = incl - v;
    if (tid == 255) g_bsum[blockIdx.x] = incl;
}

__global__ void scan2_kernel() {
    __shared__ int pref[41];
    int tid = threadIdx.x;
    if (tid == 0) {
        int s = 0;
        #pragma unroll
        for (int b = 0; b < 40; ++b) { pref[b] = s; s += g_bsum[b]; }
        pref[40] = s;
    }
    __syncthreads();
    int idx = blockIdx.x * 256 + tid;
    if (idx < NN) g_off[idx] += pref[blockIdx.x];
    if (idx == NN - 1) g_off[NN] = pref[40];
}

__global__ void scatter_kernel(const int* __restrict__ src, const int* __restrict__ dst) {
    int e = blockIdx.x * blockDim.x + threadIdx.x;
    if (e < NE) {
        int d = dst[e];
        int pos = g_off[d] + atomicAdd(&g_cnt[d], 1);
        int s = src[e];
        g_csr_src[pos] = s;
        g_csr_w[pos]   = rsqrtf((float)g_deg_out[s]);
    }
}

// fused entry: blocks [0,5000) convert x fp32->fp16; blocks [5000,5256) transpose+quantize W1
#define XCONV_BLOCKS 5000   // 1,280,000 uint2 / 256
__global__ __launch_bounds__(256) void prep_kernel(
    const float* __restrict__ x, __half* __restrict__ x16,
    const float* __restrict__ W1, __half* __restrict__ W1h)
{
    int b = blockIdx.x;
    if (b < XCONV_BLOCKS) {
        int i = b * 256 + threadIdx.x;
        float4 v = reinterpret_cast<const float4*>(x)[i];
        __half2 a = __floats2half2_rn(v.x, v.y);
        __half2 c = __floats2half2_rn(v.z, v.w);
        uint32_t ua = *reinterpret_cast<uint32_t*>(&a);
        uint32_t uc = *reinterpret_cast<uint32_t*>(&c);
        reinterpret_cast<uint2*>(x16)[i] = make_uint2(ua, uc);
    } else {
        __shared__ float t[32][33];
        int tI = b - XCONV_BLOCKS;          // 0..255 -> 16x16 tiles
        int bx = tI & 15, by = tI >> 4;
        int tx = threadIdx.x & 31, ty8 = threadIdx.x >> 5;   // 8 row-groups
        #pragma unroll
        for (int i = 0; i < 4; ++i) {
            int ty = ty8 * 4 + i;
            t[ty][tx] = W1[(size_t)(by * 32 + ty) * F + bx * 32 + tx];
        }
        __syncthreads();
        #pragma unroll
        for (int i = 0; i < 4; ++i) {
            int ty = ty8 * 4 + i;
            // Wt[n][k]: n = bx*32+ty, k = by*32+tx
            W1h[(size_t)(bx * 32 + ty) * F + by * 32 + tx] = __float2half_rn(t[tx][ty]);
        }
    }
}

// W k-major -> transposed fp16 Wt[n][k]; grid.z picks subset (W2, W3)
__global__ void wsplit_kernel(const float* __restrict__ Wa, __half* __restrict__ Oa,
                              const float* __restrict__ Wb, __half* __restrict__ Ob) {
    const float* W = (blockIdx.z == 0) ? Wa : Wb;
    __half* Oh = (blockIdx.z == 0) ? Oa : Ob;
    __shared__ float t[32][33];
    int n = blockIdx.x * 32 + threadIdx.x;
    int k = blockIdx.y * 32 + threadIdx.y;
    t[threadIdx.y][threadIdx.x] = W[(size_t)k * F + n];
    __syncthreads();
    int on = blockIdx.x * 32 + threadIdx.y;
    int ok = blockIdx.y * 32 + threadIdx.x;
    Oh[(size_t)on * F + ok] = __float2half_rn(t[threadIdx.x][threadIdx.y]);
}

// ==================== aggregation: one node per CTA (128 thr) ====================
__global__ __launch_bounds__(128) void agg_kernel(const __half* __restrict__ x,
                                                  __half* __restrict__ o,
                                                  const float* __restrict__ bias,
                                                  int relu) {
    int node = blockIdx.x;
    int tid  = threadIdx.x;
    int beg = g_off[node];
    int end = g_off[node + 1];
    const uint2* x2 = reinterpret_cast<const uint2*>(x);
    float4 acc = make_float4(0.f, 0.f, 0.f, 0.f);
    int i = beg;
    for (; i + 4 <= end; i += 4) {
        int   s0 = __ldg(&g_csr_src[i + 0]);
        int   s1 = __ldg(&g_csr_src[i + 1]);
        int   s2 = __ldg(&g_csr_src[i + 2]);
        int   s3 = __ldg(&g_csr_src[i + 3]);
        float w0 = __ldg(&g_csr_w[i + 0]);
        float w1 = __ldg(&g_csr_w[i + 1]);
        float w2 = __ldg(&g_csr_w[i + 2]);
        float w3 = __ldg(&g_csr_w[i + 3]);
        uint2 u0 = x2[(size_t)s0 * 128 + tid];
        uint2 u1 = x2[(size_t)s1 * 128 + tid];
        uint2 u2 = x2[(size_t)s2 * 128 + tid];
        uint2 u3 = x2[(size_t)s3 * 128 + tid];
        float2 a0 = __half22float2(*reinterpret_cast<__half2*>(&u0.x));
        float2 b0 = __half22float2(*reinterpret_cast<__half2*>(&u0.y));
        float2 a1 = __half22float2(*reinterpret_cast<__half2*>(&u1.x));
        float2 b1 = __half22float2(*reinterpret_cast<__half2*>(&u1.y));
        float2 a2 = __half22float2(*reinterpret_cast<__half2*>(&u2.x));
        float2 b2 = __half22float2(*reinterpret_cast<__half2*>(&u2.y));
        float2 a3 = __half22float2(*reinterpret_cast<__half2*>(&u3.x));
        float2 b3 = __half22float2(*reinterpret_cast<__half2*>(&u3.y));
        acc.x = fmaf(w0, a0.x, acc.x); acc.y = fmaf(w0, a0.y, acc.y);
        acc.z = fmaf(w0, b0.x, acc.z); acc.w = fmaf(w0, b0.y, acc.w);
        acc.x = fmaf(w1, a1.x, acc.x); acc.y = fmaf(w1, a1.y, acc.y);
        acc.z = fmaf(w1, b1.x, acc.z); acc.w = fmaf(w1, b1.y, acc.w);
        acc.x = fmaf(w2, a2.x, acc.x); acc.y = fmaf(w2, a2.y, acc.y);
        acc.z = fmaf(w2, b2.x, acc.z); acc.w = fmaf(w2, b2.y, acc.w);
        acc.x = fmaf(w3, a3.x, acc.x); acc.y = fmaf(w3, a3.y, acc.y);
        acc.z = fmaf(w3, b3.x, acc.z); acc.w = fmaf(w3, b3.y, acc.w);
    }
    for (; i < end; ++i) {
        int   s = __ldg(&g_csr_src[i]);
        float w = __ldg(&g_csr_w[i]);
        uint2 u = x2[(size_t)s * 128 + tid];
        float2 a = __half22float2(*reinterpret_cast<__half2*>(&u.x));
        float2 b = __half22float2(*reinterpret_cast<__half2*>(&u.y));
        acc.x = fmaf(w, a.x, acc.x); acc.y = fmaf(w, a.y, acc.y);
        acc.z = fmaf(w, b.x, acc.z); acc.w = fmaf(w, b.y, acc.w);
    }
    float ni = (end > beg) ? rsqrtf((float)(end - beg)) : 0.f;
    float r0 = acc.x * ni, r1 = acc.y * ni, r2 = acc.z * ni, r3 = acc.w * ni;
    if (bias) {
        float4 bv = reinterpret_cast<const float4*>(bias)[tid];
        r0 += bv.x; r1 += bv.y; r2 += bv.z; r3 += bv.w;
    }
    if (relu) {
        r0 = fmaxf(r0, 0.f); r1 = fmaxf(r1, 0.f);
        r2 = fmaxf(r2, 0.f); r3 = fmaxf(r3, 0.f);
    }
    __half2 p0 = __floats2half2_rn(r0, r1);
    __half2 p1 = __floats2half2_rn(r2, r3);
    uint2 u = make_uint2(*reinterpret_cast<uint32_t*>(&p0), *reinterpret_cast<uint32_t*>(&p1));
    reinterpret_cast<uint2*>(o + (size_t)node * F)[tid] = u;
}

// ==================== mma.sync GEMM: tile 96x128, warp 48x32 (2x4 warps) ====================
#define TM 96
#define STAGE_BYTES 28672
#define NSTAGE 3
#define GEMM_SMEM (NSTAGE * STAGE_BYTES)

__device__ __forceinline__ void load_stage(
    uint32_t s, int m0, int n0, int M, int k0, int tid,
    const __half* __restrict__ A, const __half* __restrict__ B)
{
    #pragma unroll
    for (int i = 0; i < 3; ++i) {          // A: 96 rows x 8 chunks = 768 vectors
        int v = tid + i * 256;
        int row = v >> 3, c = v & 7;
        uint32_t phys = (uint32_t)(row * 128 + ((c ^ (row & 7)) << 4));
        size_t gA = (size_t)(m0 + row) * F + k0 + c * 8;
        int sz = (m0 + row < M) ? 16 : 0;
        cp_async16(s + phys, A + gA, sz);
    }
    #pragma unroll
    for (int i = 0; i < 4; ++i) {          // B: 128 rows x 8 chunks = 1024 vectors
        int v = tid + i * 256;
        int row = v >> 3, c = v & 7;
        uint32_t phys = (uint32_t)(row * 128 + ((c ^ (row & 7)) << 4));
        size_t gB = (size_t)(n0 + row) * F + k0 + c * 8;
        cp_async16(s + 12288 + phys, B + gB, 16);
    }
    asm volatile("cp.async.commit_group;" ::: "memory");
}

__global__ __launch_bounds__(256, 2) void gemm_mma(
    const __half* __restrict__ A,
    const __half* __restrict__ B, const float* __restrict__ bias,
    float* __restrict__ C, __half* __restrict__ C16,
    const __half* __restrict__ B2, const float* __restrict__ bias2, float* __restrict__ C2,
    int M, int relu, int dual)
{
    extern __shared__ char smem[];
    const uint32_t sb = smem_to_u32(smem);
    const int tid = threadIdx.x;
    const int wid = tid >> 5, lid = tid & 31;
    int nb = blockIdx.x;
    if (dual && nb >= 4) {
        nb -= 4;
        B = B2; bias = bias2; C = C2; C16 = nullptr; relu = 0;
    }
    const int m0 = blockIdx.y * TM, n0 = nb * 128;
    const int wm = (wid & 1) * 48;
    const int wn = (wid >> 1) * 32;

    float acc[3][4][4];
    #pragma unroll
    for (int a = 0; a < 3; ++a)
        #pragma unroll
        for (int b = 0; b < 4; ++b)
            #pragma unroll
            for (int c = 0; c < 4; ++c) acc[a][b][c] = 0.f;

    load_stage(sb, m0, n0, M, 0, tid, A, B);
    load_stage(sb + STAGE_BYTES, m0, n0, M, 64, tid, A, B);

    const int NCH = F / 64;   // 8
    for (int ch = 0; ch < NCH; ++ch) {
        asm volatile("cp.async.wait_group 1;" ::: "memory");
        __syncthreads();
        if (ch + 2 < NCH)
            load_stage(sb + ((ch + 2) % NSTAGE) * STAGE_BYTES, m0, n0, M, (ch + 2) * 64, tid, A, B);
        else
            asm volatile("cp.async.commit_group;" ::: "memory");

        const uint32_t s = sb + (ch % NSTAGE) * STAGE_BYTES;
        #pragma unroll
        for (int kk = 0; kk < 4; ++kk) {
            uint32_t af[3][4];
            #pragma unroll
            for (int mt = 0; mt < 3; ++mt) {
                int row = wm + mt * 16 + (lid & 15);
                int c = kk * 2 + ((lid >> 4) & 1);
                ldsm4(af[mt], s + row * 128 + ((c ^ (row & 7)) << 4));
            }
            #pragma unroll
            for (int p = 0; p < 2; ++p) {
                int row = wn + p * 16 + (lid & 7) + (((lid >> 4) & 1) << 3);
                int c = kk * 2 + ((lid >> 3) & 1);
                uint32_t bf[4];
                ldsm4(bf, s + 12288 + row * 128 + ((c ^ (row & 7)) << 4));
                #pragma unroll
                for (int mt = 0; mt < 3; ++mt) {
                    mma_f16(acc[mt][2 * p],     af[mt], bf);
                    mma_f16(acc[mt][2 * p + 1], af[mt], bf + 2);
                }
            }
        }
        __syncthreads();
    }

    #pragma unroll
    for (int mt = 0; mt < 3; ++mt) {
        int rbase = m0 + wm + mt * 16 + (lid >> 2);
        #pragma unroll
        for (int half = 0; half < 2; ++half) {
            int m = rbase + half * 8;
            if (m < M) {
                #pragma unroll
                for (int nt = 0; nt < 4; ++nt) {
                    int n = n0 + wn + nt * 8 + (lid & 3) * 2;
                    float2 o;
                    o.x = acc[mt][nt][half * 2 + 0];
                    o.y = acc[mt][nt][half * 2 + 1];
                    if (bias) { o.x += bias[n]; o.y += bias[n + 1]; }
                    if (relu) { o.x = fmaxf(o.x, 0.f); o.y = fmaxf(o.y, 0.f); }
                    if (C)
                        *reinterpret_cast<float2*>(C + (size_t)m * F + n) = o;
                    if (C16) {
                        __half2 h = __floats2half2_rn(o.x, o.y);
                        *reinterpret_cast<__half2*>(C16 + (size_t)m * F + n) = h;
                    }
                }
            }
        }
    }
}

// ==================== launcher ====================
extern "C" void kernel_launch(void* const* d_in, const int* in_sizes, int n_in,
                              void* d_out, int out_size) {
    const float* x   = (const float*)d_in[0];
    const float* W1  = (const float*)d_in[1];
    const float* b1  = (const float*)d_in[2];
    const float* W2  = (const float*)d_in[3];
    const float* b2  = (const float*)d_in[4];
    const float* W3  = (const float*)d_in[5];
    const float* b3  = (const float*)d_in[6];
    const int*   src = (const int*)d_in[7];
    const int*   dst = (const int*)d_in[8];

    float* out = (float*)d_out;
    float* h4 = out;
    float* h3 = out + (size_t)NN * F;
    float* h2 = out + 2 * (size_t)NN * F;

    void* ivec = nullptr;
    __half *x16 = nullptr, *hf16 = nullptr, *A16 = nullptr;
    __half *W1h = nullptr, *W2h = nullptr, *W3h = nullptr;
    cudaGetSymbolAddress(&ivec, g_ivec);
    cudaGetSymbolAddress((void**)&x16,  g_x16);
    cudaGetSymbolAddress((void**)&hf16, g_hf16);
    cudaGetSymbolAddress((void**)&A16,  g_A16);
    cudaGetSymbolAddress((void**)&W1h, g_W1h);
    cudaGetSymbolAddress((void**)&W2h, g_W2h);
    cudaGetSymbolAddress((void**)&W3h, g_W3h);

    cudaFuncSetAttribute(gemm_mma, cudaFuncAttributeMaxDynamicSharedMemorySize, GEMM_SMEM);

    // ONE side stream (proven safe); three events
    cudaStream_t s1;
    cudaStreamCreateWithFlags(&s1, cudaStreamNonBlocking);
    cudaEvent_t evFork, evY1, evW23;
    cudaEventCreateWithFlags(&evFork, cudaEventDisableTiming);
    cudaEventCreateWithFlags(&evY1, cudaEventDisableTiming);
    cudaEventCreateWithFlags(&evW23, cudaEventDisableTiming);

    const int TB = 256;
    const int MB = (NN + TM - 1) / TM;   // 105 M-blocks
    dim3 ggrid(4, MB);
    dim3 ggrid2(8, MB);

    // ---- side stream: fused prep (xconv + W1 split) + Y1 GEMM; W2/W3 split after ----
    cudaEventRecord(evFork, 0);
    cudaStreamWaitEvent(s1, evFork, 0);
    prep_kernel<<<XCONV_BLOCKS + 256, 256, 0, s1>>>(x, x16, W1, W1h);
    gemm_mma<<<ggrid, 256, GEMM_SMEM, s1>>>(x16, W1h, nullptr, nullptr, A16,
                                            nullptr, nullptr, nullptr, NN, 0, 0);
    cudaEventRecord(evY1, s1);                       // Y1 ready (critical)
    wsplit_kernel<<<dim3(16, 16, 2), dim3(32, 32), 0, s1>>>(W2, W2h, W3, W3h);
    cudaEventRecord(evW23, s1);                      // hidden under agg1+agg2

    // ---- main stream: CSR build (parallel with the Y1 chain) ----
    cudaMemsetAsync(ivec, 0, sizeof(int) * 3 * NN, 0);
    degree_kernel<<<(NE + TB - 1) / TB, TB>>>(src, dst);
    scan1_kernel<<<40, 256>>>();
    scan2_kernel<<<40, 256>>>();
    scatter_kernel<<<(NE + TB - 1) / TB, TB>>>(src, dst);
    cudaStreamWaitEvent(0, evY1, 0);

    // layer 1: h1 = relu(Agg(Y1) + b1)     [linearity: Agg(X)W1 = Agg(X W1)]
    agg_kernel<<<NN, 128>>>(A16, hf16, b1, 1);
    // layer 2: h2 = relu(Agg(h1) W2 + b2)  -> fp32 d_out + fp16 x16
    agg_kernel<<<NN, 128>>>(hf16, A16, nullptr, 0);
    cudaStreamWaitEvent(0, evW23, 0);
    gemm_mma<<<ggrid, 256, GEMM_SMEM>>>(A16, W2h, b2, h2, x16,
                                        nullptr, nullptr, nullptr, NN, 1, 0);
    // layer 3: shared agg feeds h3 (W2,relu) + h4 (W3) in one dual GEMM
    agg_kernel<<<NN, 128>>>(x16, A16, nullptr, 0);
    gemm_mma<<<ggrid2, 256, GEMM_SMEM>>>(A16, W2h, b2, h3, nullptr,
                                         W3h, b3, h4, NN, 1, 1);
}

// round 17
// speedup vs baseline: 1.0952x; 1.0017x over previous
#include <cuda_runtime.h>
#include <cuda_fp16.h>
#include <cstdint>

#define NN 10000
#define NE 160000
#define F 512

// ==================== scratch (device globals) ====================
// one contiguous zeroed region: deg_out, deg_in, cnt, bsum(40), bflag(40)
#define ZN (3 * NN + 128)
__device__ int g_zero[ZN];
#define g_deg_out (g_zero)
#define g_deg_in  (g_zero + NN)
#define g_cnt     (g_zero + 2 * NN)
#define g_bsum    (g_zero + 3 * NN)
#define g_bflag   (g_zero + 3 * NN + 64)
__device__ int   g_off[NN + 1];
__device__ int   g_csr_src[NE];
__device__ float g_csr_w[NE];
__device__ __half g_x16[(size_t)NN * F];    // fp16 x, later fp16 h2
__device__ __half g_hf16[(size_t)NN * F];   // fp16 h1
__device__ __half g_A16[(size_t)NN * F];    // Y1, then aggregated GEMM A operand
__device__ __half g_W1h[F * F], g_W2h[F * F], g_W3h[F * F];

// ==================== PTX helpers ====================
__device__ __forceinline__ uint32_t smem_to_u32(const void* p) {
    uint32_t a;
    asm("{ .reg .u64 t; cvta.to.shared.u64 t, %1; cvt.u32.u64 %0, t; }" : "=r"(a) : "l"(p));
    return a;
}
__device__ __forceinline__ void cp_async16(uint32_t dst, const void* src, int sz) {
    asm volatile("cp.async.cg.shared.global [%0], [%1], 16, %2;"
        :: "r"(dst), "l"(src), "r"(sz) : "memory");
}
__device__ __forceinline__ void ldsm4(uint32_t* r, uint32_t addr) {
    asm volatile("ldmatrix.sync.aligned.m8n8.x4.shared.b16 {%0,%1,%2,%3}, [%4];"
        : "=r"(r[0]), "=r"(r[1]), "=r"(r[2]), "=r"(r[3]) : "r"(addr));
}
__device__ __forceinline__ void mma_f16(float* d, const uint32_t* a, const uint32_t* b) {
    asm volatile(
        "mma.sync.aligned.m16n8k16.row.col.f32.f16.f16.f32 "
        "{%0,%1,%2,%3}, {%4,%5,%6,%7}, {%8,%9}, {%0,%1,%2,%3};"
        : "+f"(d[0]), "+f"(d[1]), "+f"(d[2]), "+f"(d[3])
        : "r"(a[0]), "r"(a[1]), "r"(a[2]), "r"(a[3]), "r"(b[0]), "r"(b[1]));
}

// ==================== setup kernels ====================
// 4 edges per thread (int4); latency-bound before, MLP=8 now
__global__ void degree_kernel(const int* __restrict__ src, const int* __restrict__ dst) {
    int i = blockIdx.x * blockDim.x + threadIdx.x;
    if (i < NE / 4) {
        int4 s = reinterpret_cast<const int4*>(src)[i];
        int4 d = reinterpret_cast<const int4*>(dst)[i];
        atomicAdd(&g_deg_out[s.x], 1); atomicAdd(&g_deg_out[s.y], 1);
        atomicAdd(&g_deg_out[s.z], 1); atomicAdd(&g_deg_out[s.w], 1);
        atomicAdd(&g_deg_in[d.x], 1);  atomicAdd(&g_deg_in[d.y], 1);
        atomicAdd(&g_deg_in[d.z], 1);  atomicAdd(&g_deg_in[d.w], 1);
    }
}

// single-pass exclusive scan with decoupled lookback (40 blocks, all resident)
__global__ void scan_kernel() {
    __shared__ int wsum[8];
    __shared__ int s_pref;
    int tid = threadIdx.x, b = blockIdx.x;
    int idx = b * 256 + tid;
    int v = (idx < NN) ? g_deg_in[idx] : 0;
    int x = v;
    #pragma unroll
    for (int d = 1; d < 32; d <<= 1) {
        int y = __shfl_up_sync(0xffffffffu, x, d);
        if ((tid & 31) >= d) x += y;
    }
    if ((tid & 31) == 31) wsum[tid >> 5] = x;
    if (tid == 0) s_pref = 0;
    __syncthreads();
    if (tid < 8) {
        int w = wsum[tid];
        #pragma unroll
        for (int d = 1; d < 8; d <<= 1) {
            int y = __shfl_up_sync(0xffu, w, d);
            if (tid >= d) w += y;
        }
        wsum[tid] = w;
    }
    __syncthreads();
    int incl = x + ((tid >= 32) ? wsum[(tid >> 5) - 1] : 0);
    // publish block total
    if (tid == 255) {
        g_bsum[b] = incl;
        __threadfence();
        atomicExch(&g_bflag[b], 1);
    }
    // lookback: thread t < b waits for block t's total
    if (tid < b) {
        volatile int* fl = (volatile int*)&g_bflag[tid];
        while (*fl == 0) {}
        atomicAdd_block(&s_pref, g_bsum[tid]);
    }
    __syncthreads();
    int pre = s_pref;
    if (idx <= NN) g_off[idx] = pre + incl - v;   // exclusive (covers g_off[NN] at idx==NN)
}

// 2 edges per thread
__global__ void scatter_kernel(const int* __restrict__ src, const int* __restrict__ dst) {
    int i = blockIdx.x * blockDim.x + threadIdx.x;
    if (i < NE / 2) {
        int2 s2 = reinterpret_cast<const int2*>(src)[i];
        int2 d2 = reinterpret_cast<const int2*>(dst)[i];
        int p0 = g_off[d2.x] + atomicAdd(&g_cnt[d2.x], 1);
        g_csr_src[p0] = s2.x;
        g_csr_w[p0]   = rsqrtf((float)g_deg_out[s2.x]);
        int p1 = g_off[d2.y] + atomicAdd(&g_cnt[d2.y], 1);
        g_csr_src[p1] = s2.y;
        g_csr_w[p1]   = rsqrtf((float)g_deg_out[s2.y]);
    }
}

// fused entry: blocks [0,5000) convert x fp32->fp16; blocks [5000,5256) transpose+quantize W1
#define XCONV_BLOCKS 5000
__global__ __launch_bounds__(256) void prep_kernel(
    const float* __restrict__ x, __half* __restrict__ x16,
    const float* __restrict__ W1, __half* __restrict__ W1h)
{
    int b = blockIdx.x;
    if (b < XCONV_BLOCKS) {
        int i = b * 256 + threadIdx.x;
        float4 v = reinterpret_cast<const float4*>(x)[i];
        __half2 a = __floats2half2_rn(v.x, v.y);
        __half2 c = __floats2half2_rn(v.z, v.w);
        uint32_t ua = *reinterpret_cast<uint32_t*>(&a);
        uint32_t uc = *reinterpret_cast<uint32_t*>(&c);
        reinterpret_cast<uint2*>(x16)[i] = make_uint2(ua, uc);
    } else {
        __shared__ float t[32][33];
        int tI = b - XCONV_BLOCKS;
        int bx = tI & 15, by = tI >> 4;
        int tx = threadIdx.x & 31, ty8 = threadIdx.x >> 5;
        #pragma unroll
        for (int i = 0; i < 4; ++i) {
            int ty = ty8 * 4 + i;
            t[ty][tx] = W1[(size_t)(by * 32 + ty) * F + bx * 32 + tx];
        }
        __syncthreads();
        #pragma unroll
        for (int i = 0; i < 4; ++i) {
            int ty = ty8 * 4 + i;
            W1h[(size_t)(bx * 32 + ty) * F + by * 32 + tx] = __float2half_rn(t[tx][ty]);
        }
    }
}

// W k-major -> transposed fp16 Wt[n][k]; grid.z picks subset (W2, W3)
__global__ void wsplit_kernel(const float* __restrict__ Wa, __half* __restrict__ Oa,
                              const float* __restrict__ Wb, __half* __restrict__ Ob) {
    const float* W = (blockIdx.z == 0) ? Wa : Wb;
    __half* Oh = (blockIdx.z == 0) ? Oa : Ob;
    __shared__ float t[32][33];
    int n = blockIdx.x * 32 + threadIdx.x;
    int k = blockIdx.y * 32 + threadIdx.y;
    t[threadIdx.y][threadIdx.x] = W[(size_t)k * F + n];
    __syncthreads();
    int on = blockIdx.x * 32 + threadIdx.y;
    int ok = blockIdx.y * 32 + threadIdx.x;
    Oh[(size_t)on * F + ok] = __float2half_rn(t[threadIdx.x][threadIdx.y]);
}

// ==================== aggregation: one node per CTA (128 thr) ====================
__global__ __launch_bounds__(128) void agg_kernel(const __half* __restrict__ x,
                                                  __half* __restrict__ o,
                                                  const float* __restrict__ bias,
                                                  int relu) {
    int node = blockIdx.x;
    int tid  = threadIdx.x;
    int beg = g_off[node];
    int end = g_off[node + 1];
    const uint2* x2 = reinterpret_cast<const uint2*>(x);
    float4 acc = make_float4(0.f, 0.f, 0.f, 0.f);
    int i = beg;
    for (; i + 4 <= end; i += 4) {
        int   s0 = __ldg(&g_csr_src[i + 0]);
        int   s1 = __ldg(&g_csr_src[i + 1]);
        int   s2 = __ldg(&g_csr_src[i + 2]);
        int   s3 = __ldg(&g_csr_src[i + 3]);
        float w0 = __ldg(&g_csr_w[i + 0]);
        float w1 = __ldg(&g_csr_w[i + 1]);
        float w2 = __ldg(&g_csr_w[i + 2]);
        float w3 = __ldg(&g_csr_w[i + 3]);
        uint2 u0 = x2[(size_t)s0 * 128 + tid];
        uint2 u1 = x2[(size_t)s1 * 128 + tid];
        uint2 u2 = x2[(size_t)s2 * 128 + tid];
        uint2 u3 = x2[(size_t)s3 * 128 + tid];
        float2 a0 = __half22float2(*reinterpret_cast<__half2*>(&u0.x));
        float2 b0 = __half22float2(*reinterpret_cast<__half2*>(&u0.y));
        float2 a1 = __half22float2(*reinterpret_cast<__half2*>(&u1.x));
        float2 b1 = __half22float2(*reinterpret_cast<__half2*>(&u1.y));
        float2 a2 = __half22float2(*reinterpret_cast<__half2*>(&u2.x));
        float2 b2 = __half22float2(*reinterpret_cast<__half2*>(&u2.y));
        float2 a3 = __half22float2(*reinterpret_cast<__half2*>(&u3.x));
        float2 b3 = __half22float2(*reinterpret_cast<__half2*>(&u3.y));
        acc.x = fmaf(w0, a0.x, acc.x); acc.y = fmaf(w0, a0.y, acc.y);
        acc.z = fmaf(w0, b0.x, acc.z); acc.w = fmaf(w0, b0.y, acc.w);
        acc.x = fmaf(w1, a1.x, acc.x); acc.y = fmaf(w1, a1.y, acc.y);
        acc.z = fmaf(w1, b1.x, acc.z); acc.w = fmaf(w1, b1.y, acc.w);
        acc.x = fmaf(w2, a2.x, acc.x); acc.y = fmaf(w2, a2.y, acc.y);
        acc.z = fmaf(w2, b2.x, acc.z); acc.w = fmaf(w2, b2.y, acc.w);
        acc.x = fmaf(w3, a3.x, acc.x); acc.y = fmaf(w3, a3.y, acc.y);
        acc.z = fmaf(w3, b3.x, acc.z); acc.w = fmaf(w3, b3.y, acc.w);
    }
    for (; i < end; ++i) {
        int   s = __ldg(&g_csr_src[i]);
        float w = __ldg(&g_csr_w[i]);
        uint2 u = x2[(size_t)s * 128 + tid];
        float2 a = __half22float2(*reinterpret_cast<__half2*>(&u.x));
        float2 b = __half22float2(*reinterpret_cast<__half2*>(&u.y));
        acc.x = fmaf(w, a.x, acc.x); acc.y = fmaf(w, a.y, acc.y);
        acc.z = fmaf(w, b.x, acc.z); acc.w = fmaf(w, b.y, acc.w);
    }
    float ni = (end > beg) ? rsqrtf((float)(end - beg)) : 0.f;
    float r0 = acc.x * ni, r1 = acc.y * ni, r2 = acc.z * ni, r3 = acc.w * ni;
    if (bias) {
        float4 bv = reinterpret_cast<const float4*>(bias)[tid];
        r0 += bv.x; r1 += bv.y; r2 += bv.z; r3 += bv.w;
    }
    if (relu) {
        r0 = fmaxf(r0, 0.f); r1 = fmaxf(r1, 0.f);
        r2 = fmaxf(r2, 0.f); r3 = fmaxf(r3, 0.f);
    }
    __half2 p0 = __floats2half2_rn(r0, r1);
    __half2 p1 = __floats2half2_rn(r2, r3);
    uint2 u = make_uint2(*reinterpret_cast<uint32_t*>(&p0), *reinterpret_cast<uint32_t*>(&p1));
    reinterpret_cast<uint2*>(o + (size_t)node * F)[tid] = u;
}

// ==================== mma.sync GEMM: tile 96x128, warp 48x32 (2x4 warps) ====================
#define TM 96
#define STAGE_BYTES 28672
#define NSTAGE 3
#define GEMM_SMEM (NSTAGE * STAGE_BYTES)

__device__ __forceinline__ void load_stage(
    uint32_t s, int m0, int n0, int M, int k0, int tid,
    const __half* __restrict__ A, const __half* __restrict__ B)
{
    #pragma unroll
    for (int i = 0; i < 3; ++i) {
        int v = tid + i * 256;
        int row = v >> 3, c = v & 7;
        uint32_t phys = (uint32_t)(row * 128 + ((c ^ (row & 7)) << 4));
        size_t gA = (size_t)(m0 + row) * F + k0 + c * 8;
        int sz = (m0 + row < M) ? 16 : 0;
        cp_async16(s + phys, A + gA, sz);
    }
    #pragma unroll
    for (int i = 0; i < 4; ++i) {
        int v = tid + i * 256;
        int row = v >> 3, c = v & 7;
        uint32_t phys = (uint32_t)(row * 128 + ((c ^ (row & 7)) << 4));
        size_t gB = (size_t)(n0 + row) * F + k0 + c * 8;
        cp_async16(s + 12288 + phys, B + gB, 16);
    }
    asm volatile("cp.async.commit_group;" ::: "memory");
}

__global__ __launch_bounds__(256, 2) void gemm_mma(
    const __half* __restrict__ A,
    const __half* __restrict__ B, const float* __restrict__ bias,
    float* __restrict__ C, __half* __restrict__ C16,
    const __half* __restrict__ B2, const float* __restrict__ bias2, float* __restrict__ C2,
    int M, int relu, int dual)
{
    extern __shared__ char smem[];
    const uint32_t sb = smem_to_u32(smem);
    const int tid = threadIdx.x;
    const int wid = tid >> 5, lid = tid & 31;
    int nb = blockIdx.x;
    if (dual && nb >= 4) {
        nb -= 4;
        B = B2; bias = bias2; C = C2; C16 = nullptr; relu = 0;
    }
    const int m0 = blockIdx.y * TM, n0 = nb * 128;
    const int wm = (wid & 1) * 48;
    const int wn = (wid >> 1) * 32;

    float acc[3][4][4];
    #pragma unroll
    for (int a = 0; a < 3; ++a)
        #pragma unroll
        for (int b = 0; b < 4; ++b)
            #pragma unroll
            for (int c = 0; c < 4; ++c) acc[a][b][c] = 0.f;

    load_stage(sb, m0, n0, M, 0, tid, A, B);
    load_stage(sb + STAGE_BYTES, m0, n0, M, 64, tid, A, B);

    const int NCH = F / 64;   // 8
    for (int ch = 0; ch < NCH; ++ch) {
        asm volatile("cp.async.wait_group 1;" ::: "memory");
        __syncthreads();
        if (ch + 2 < NCH)
            load_stage(sb + ((ch + 2) % NSTAGE) * STAGE_BYTES, m0, n0, M, (ch + 2) * 64, tid, A, B);
        else
            asm volatile("cp.async.commit_group;" ::: "memory");

        const uint32_t s = sb + (ch % NSTAGE) * STAGE_BYTES;
        #pragma unroll
        for (int kk = 0; kk < 4; ++kk) {
            uint32_t af[3][4];
            #pragma unroll
            for (int mt = 0; mt < 3; ++mt) {
                int row = wm + mt * 16 + (lid & 15);
                int c = kk * 2 + ((lid >> 4) & 1);
                ldsm4(af[mt], s + row * 128 + ((c ^ (row & 7)) << 4));
            }
            #pragma unroll
            for (int p = 0; p < 2; ++p) {
                int row = wn + p * 16 + (lid & 7) + (((lid >> 4) & 1) << 3);
                int c = kk * 2 + ((lid >> 3) & 1);
                uint32_t bf[4];
                ldsm4(bf, s + 12288 + row * 128 + ((c ^ (row & 7)) << 4));
                #pragma unroll
                for (int mt = 0; mt < 3; ++mt) {
                    mma_f16(acc[mt][2 * p],     af[mt], bf);
                    mma_f16(acc[mt][2 * p + 1], af[mt], bf + 2);
                }
            }
        }
        __syncthreads();
    }

    #pragma unroll
    for (int mt = 0; mt < 3; ++mt) {
        int rbase = m0 + wm + mt * 16 + (lid >> 2);
        #pragma unroll
        for (int half = 0; half < 2; ++half) {
            int m = rbase + half * 8;
            if (m < M) {
                #pragma unroll
                for (int nt = 0; nt < 4; ++nt) {
                    int n = n0 + wn + nt * 8 + (lid & 3) * 2;
                    float2 o;
                    o.x = acc[mt][nt][half * 2 + 0];
                    o.y = acc[mt][nt][half * 2 + 1];
                    if (bias) { o.x += bias[n]; o.y += bias[n + 1]; }
                    if (relu) { o.x = fmaxf(o.x, 0.f); o.y = fmaxf(o.y, 0.f); }
                    if (C)
                        *reinterpret_cast<float2*>(C + (size_t)m * F + n) = o;
                    if (C16) {
                        __half2 h = __floats2half2_rn(o.x, o.y);
                        *reinterpret_cast<__half2*>(C16 + (size_t)m * F + n) = h;
                    }
                }
            }
        }
    }
}

// ==================== launcher ====================
extern "C" void kernel_launch(void* const* d_in, const int* in_sizes, int n_in,
                              void* d_out, int out_size) {
    const float* x   = (const float*)d_in[0];
    const float* W1  = (const float*)d_in[1];
    const float* b1  = (const float*)d_in[2];
    const float* W2  = (const float*)d_in[3];
    const float* b2  = (const float*)d_in[4];
    const float* W3  = (const float*)d_in[5];
    const float* b3  = (const float*)d_in[6];
    const int*   src = (const int*)d_in[7];
    const int*   dst = (const int*)d_in[8];

    float* out = (float*)d_out;
    float* h4 = out;
    float* h3 = out + (size_t)NN * F;
    float* h2 = out + 2 * (size_t)NN * F;

    void* zreg = nullptr;
    __half *x16 = nullptr, *hf16 = nullptr, *A16 = nullptr;
    __half *W1h = nullptr, *W2h = nullptr, *W3h = nullptr;
    cudaGetSymbolAddress(&zreg, g_zero);
    cudaGetSymbolAddress((void**)&x16,  g_x16);
    cudaGetSymbolAddress((void**)&hf16, g_hf16);
    cudaGetSymbolAddress((void**)&A16,  g_A16);
    cudaGetSymbolAddress((void**)&W1h, g_W1h);
    cudaGetSymbolAddress((void**)&W2h, g_W2h);
    cudaGetSymbolAddress((void**)&W3h, g_W3h);

    cudaFuncSetAttribute(gemm_mma, cudaFuncAttributeMaxDynamicSharedMemorySize, GEMM_SMEM);

    // ONE side stream (proven safe); three events
    cudaStream_t s1;
    cudaStreamCreateWithFlags(&s1, cudaStreamNonBlocking);
    cudaEvent_t evFork, evY1, evW23;
    cudaEventCreateWithFlags(&evFork, cudaEventDisableTiming);
    cudaEventCreateWithFlags(&evY1, cudaEventDisableTiming);
    cudaEventCreateWithFlags(&evW23, cudaEventDisableTiming);

    const int MB = (NN + TM - 1) / TM;   // 105 M-blocks
    dim3 ggrid(4, MB);
    dim3 ggrid2(8, MB);

    // ---- side stream: fused prep (xconv + W1 split) + Y1 GEMM; W2/W3 split after ----
    cudaEventRecord(evFork, 0);
    cudaStreamWaitEvent(s1, evFork, 0);
    prep_kernel<<<XCONV_BLOCKS + 256, 256, 0, s1>>>(x, x16, W1, W1h);
    gemm_mma<<<ggrid, 256, GEMM_SMEM, s1>>>(x16, W1h, nullptr, nullptr, A16,
                                            nullptr, nullptr, nullptr, NN, 0, 0);
    cudaEventRecord(evY1, s1);                       // Y1 ready (critical)
    wsplit_kernel<<<dim3(16, 16, 2), dim3(32, 32), 0, s1>>>(W2, W2h, W3, W3h);
    cudaEventRecord(evW23, s1);                      // hidden under agg1+agg2

    // ---- main stream: CSR build (time-shared with the Y1 chain) ----
    cudaMemsetAsync(zreg, 0, sizeof(int) * ZN, 0);
    degree_kernel<<<(NE / 4 + 255) / 256, 256>>>(src, dst);
    scan_kernel<<<40, 256>>>();
    scatter_kernel<<<(NE / 2 + 255) / 256, 256>>>(src, dst);
    cudaStreamWaitEvent(0, evY1, 0);

    // layer 1: h1 = relu(Agg(Y1) + b1)     [linearity: Agg(X)W1 = Agg(X W1)]
    agg_kernel<<<NN, 128>>>(A16, hf16, b1, 1);
    // layer 2: h2 = relu(Agg(h1) W2 + b2)  -> fp32 d_out + fp16 x16
    agg_kernel<<<NN, 128>>>(hf16, A16, nullptr, 0);
    cudaStreamWaitEvent(0, evW23, 0);
    gemm_mma<<<ggrid, 256, GEMM_SMEM>>>(A16, W2h, b2, h2, x16,
                                        nullptr, nullptr, nullptr, NN, 1, 0);
    // layer 3: shared agg feeds h3 (W2,relu) + h4 (W3) in one dual GEMM
    agg_kernel<<<NN, 128>>>(x16, A16, nullptr, 0);
    gemm_mma<<<ggrid2, 256, GEMM_SMEM>>>(A16, W2h, b2, h3, nullptr,
                                         W3h, b3, h4, NN, 1, 1);
}